// round 1
// baseline (speedup 1.0000x reference)
#include <cuda_runtime.h>

#define DIM 768
#define HEADS 12
#define HD 64
#define G 48
#define NTOK 2304   // G*G
#define RANK 8
#define NT 36       // NTOK/64

// ---------------- scratch (device globals; no allocation allowed) ----------
__device__ __align__(16) float g_Wq[DIM*DIM];
__device__ __align__(16) float g_Wk[DIM*DIM];
__device__ __align__(16) float g_Wv[DIM*DIM];
__device__ __align__(16) float g_q[HEADS*NTOK*HD];
__device__ __align__(16) float g_k[HEADS*NTOK*HD];
__device__ __align__(16) float g_v[HEADS*NTOK*HD];
__device__ __align__(16) float g_relh[HEADS*NTOK*G];
__device__ __align__(16) float g_relw[HEADS*NTOK*G];
__device__ __align__(16) float g_ao[NTOK*DIM];

// ---------------- kernel 1: fold LoRA into weights -------------------------
__global__ __launch_bounds__(256) void fuse_w(
    const float* __restrict__ Wq, const float* __restrict__ Aq, const float* __restrict__ Bq,
    const float* __restrict__ Wk, const float* __restrict__ Ak, const float* __restrict__ Bk,
    const float* __restrict__ Wv, const float* __restrict__ Av, const float* __restrict__ Bv)
{
    int idx = blockIdx.x * 256 + threadIdx.x;
    if (idx >= 3 * DIM * DIM) return;
    int which = idx / (DIM * DIM);
    int rem = idx - which * (DIM * DIM);
    int i = rem / DIM, j = rem - i * DIM;
    const float *W, *A, *B;
    float* O;
    if (which == 0)      { W = Wq; A = Aq; B = Bq; O = g_Wq; }
    else if (which == 1) { W = Wk; A = Ak; B = Bk; O = g_Wk; }
    else                 { W = Wv; A = Av; B = Bv; O = g_Wv; }
    float v = W[rem];
#pragma unroll
    for (int r = 0; r < RANK; r++) v += A[i * RANK + r] * B[r * DIM + j];
    O[rem] = v;
}

// ---------------- shared SGEMM tile engine (128x128x16, 8x8 microtile) -----
__device__ __forceinline__ void gemm_tile(const float* __restrict__ A,
                                          const float* __restrict__ B,
                                          float acc[8][8])
{
    __shared__ float Ash[16][128];
    __shared__ float Bsh[16][128];
    int tid = threadIdx.x;
    int tx = tid & 15, ty = tid >> 4;
    int row0 = ty * 8, col0 = tx * 8;
    const float* Ab = A + (blockIdx.y * 128) * DIM;
    const float* Bb = B + blockIdx.x * 128;

    for (int k0 = 0; k0 < DIM; k0 += 16) {
        // A tile 128x16, stored transposed Ash[k][row]
#pragma unroll
        for (int s = 0; s < 2; s++) {
            int id = tid + s * 256;            // 512 float4
            int r = id >> 2, c4 = (id & 3) * 4;
            float4 a = *(const float4*)(Ab + r * DIM + k0 + c4);
            Ash[c4 + 0][r] = a.x; Ash[c4 + 1][r] = a.y;
            Ash[c4 + 2][r] = a.z; Ash[c4 + 3][r] = a.w;
        }
        // B tile 16x128, row-major
#pragma unroll
        for (int s = 0; s < 2; s++) {
            int id = tid + s * 256;
            int r = id >> 5, c4 = (id & 31) * 4;
            *(float4*)(&Bsh[r][c4]) = *(const float4*)(Bb + (k0 + r) * DIM + c4);
        }
        __syncthreads();
#pragma unroll
        for (int k = 0; k < 16; k++) {
            float af[8], bf[8];
#pragma unroll
            for (int i = 0; i < 8; i++) af[i] = Ash[k][row0 + i];
#pragma unroll
            for (int j = 0; j < 8; j++) bf[j] = Bsh[k][col0 + j];
#pragma unroll
            for (int i = 0; i < 8; i++)
#pragma unroll
                for (int j = 0; j < 8; j++) acc[i][j] += af[i] * bf[j];
        }
        __syncthreads();
    }
}

// ---------------- kernel 2: QKV GEMM (writes head-major layout) ------------
__global__ __launch_bounds__(256) void gemm_qkv(
    const float* __restrict__ x,
    const float* __restrict__ bq, const float* __restrict__ bk, const float* __restrict__ bv)
{
    float acc[8][8] = {};
    const float *W, *bias;
    float* outp;
    int z = blockIdx.z;
    if (z == 0)      { W = g_Wq; bias = bq; outp = g_q; }
    else if (z == 1) { W = g_Wk; bias = bk; outp = g_k; }
    else             { W = g_Wv; bias = bv; outp = g_v; }
    gemm_tile(x, W, acc);
    int tid = threadIdx.x;
    int tx = tid & 15, ty = tid >> 4;
    int gr0 = blockIdx.y * 128 + ty * 8;
    int gc0 = blockIdx.x * 128 + tx * 8;
#pragma unroll
    for (int i = 0; i < 8; i++)
#pragma unroll
        for (int j = 0; j < 8; j++) {
            int gc = gc0 + j;
            int h = gc >> 6, c = gc & 63;
            outp[h * (NTOK * HD) + (gr0 + i) * HD + c] = acc[i][j] + bias[gc];
        }
}

// ---------------- kernel 5: output projection ------------------------------
__global__ __launch_bounds__(256) void gemm_proj(
    const float* __restrict__ Wp, const float* __restrict__ bp, float* __restrict__ out)
{
    float acc[8][8] = {};
    gemm_tile(g_ao, Wp, acc);
    int tid = threadIdx.x;
    int tx = tid & 15, ty = tid >> 4;
    int gr0 = blockIdx.y * 128 + ty * 8;
    int gc0 = blockIdx.x * 128 + tx * 8;
#pragma unroll
    for (int i = 0; i < 8; i++)
#pragma unroll
        for (int j = 0; j < 8; j++) {
            int gc = gc0 + j;
            out[(gr0 + i) * DIM + gc] = acc[i][j] + bp[gc];
        }
}

// ---------------- kernel 3: rel-pos dot tables -----------------------------
// relh[h,n,kh] = sum_c q[h,n,c] * rel_pos_h[(n/48 - kh + 47), c]
__global__ __launch_bounds__(128) void rel_kernel(
    const float* __restrict__ rph, const float* __restrict__ rpw)
{
    int n = blockIdx.x;
    int head = blockIdx.y;
    __shared__ float qs[HD];
    int tid = threadIdx.x;
    if (tid < HD) qs[tid] = g_q[head * (NTOK * HD) + n * HD + tid];
    __syncthreads();
    int hq = n / G;
    int wq = n - hq * G;
    if (tid < G) {
        const float* row = rph + (hq - tid + G - 1) * HD;
        float s = 0.f;
#pragma unroll 16
        for (int c = 0; c < HD; c++) s += qs[c] * row[c];
        g_relh[(head * NTOK + n) * G + tid] = s;
    } else if (tid >= 64 && tid < 64 + G) {
        int kw = tid - 64;
        const float* row = rpw + (wq - kw + G - 1) * HD;
        float s = 0.f;
#pragma unroll 16
        for (int c = 0; c < HD; c++) s += qs[c] * row[c];
        g_relw[(head * NTOK + n) * G + kw] = s;
    }
}

// ---------------- kernel 4: flash attention with decomposed bias -----------
#define LDP 65   // padded row stride
__global__ __launch_bounds__(256) void flash_kernel()
{
    extern __shared__ float sm[];
    float* Qs = sm;                     // 64*65
    float* Ks = Qs + 64 * LDP;
    float* Vs = Ks + 64 * LDP;
    float* Ps = Vs + 64 * LDP;
    float* rh = Ps + 64 * LDP;          // 64*48 (flat)
    float* rw = rh + 64 * G;
    float* m_s = rw + 64 * G;           // 64
    float* l_s = m_s + 64;
    float* al_s = l_s + 64;

    int tile = blockIdx.x, head = blockIdx.y;
    int tid = threadIdx.x;
    int tc = tid & 15, tr = tid >> 4;
    int R = tr * 4, C4 = tc * 4;
    const float scale = 0.125f;         // 64^-0.5

    // load Q (pre-scaled)
    const float* qb = g_q + head * (NTOK * HD) + tile * 64 * HD;
#pragma unroll
    for (int s = 0; s < 4; s++) {
        int id4 = tid + s * 256;        // 1024 float4
        float4 v = *(const float4*)(qb + id4 * 4);
        int r = id4 >> 4;
        int c = (id4 & 15) * 4;
        Qs[r * LDP + c + 0] = v.x * scale;
        Qs[r * LDP + c + 1] = v.y * scale;
        Qs[r * LDP + c + 2] = v.z * scale;
        Qs[r * LDP + c + 3] = v.w * scale;
    }
    // load rel tables (contiguous copies)
    const float* rhb = g_relh + (head * NTOK + tile * 64) * G;
    const float* rwb = g_relw + (head * NTOK + tile * 64) * G;
#pragma unroll
    for (int s = 0; s < 3; s++) {
        int id4 = tid + s * 256;        // 768 float4 = 3072 floats
        ((float4*)rh)[id4] = ((const float4*)rhb)[id4];
        ((float4*)rw)[id4] = ((const float4*)rwb)[id4];
    }
    if (tid < 64) { m_s[tid] = -1e30f; l_s[tid] = 0.f; }

    float acc[4][4] = {};

    for (int kt = 0; kt < NT; kt++) {
        __syncthreads();   // protects Ks/Vs/Ps reuse + first-iter init
        const float* kb = g_k + head * (NTOK * HD) + kt * 64 * HD;
        const float* vb = g_v + head * (NTOK * HD) + kt * 64 * HD;
#pragma unroll
        for (int s = 0; s < 4; s++) {
            int id4 = tid + s * 256;
            int r = id4 >> 4;
            int c = (id4 & 15) * 4;
            float4 k4 = *(const float4*)(kb + id4 * 4);
            Ks[r * LDP + c + 0] = k4.x; Ks[r * LDP + c + 1] = k4.y;
            Ks[r * LDP + c + 2] = k4.z; Ks[r * LDP + c + 3] = k4.w;
            float4 v4 = *(const float4*)(vb + id4 * 4);
            Vs[r * LDP + c + 0] = v4.x; Vs[r * LDP + c + 1] = v4.y;
            Vs[r * LDP + c + 2] = v4.z; Vs[r * LDP + c + 3] = v4.w;
        }
        __syncthreads();

        // S = Qs * Ks^T (4x4 microtile per thread)
        float s4[4][4] = {};
#pragma unroll 16
        for (int c = 0; c < 64; c++) {
            float qf[4], kf[4];
#pragma unroll
            for (int i = 0; i < 4; i++) qf[i] = Qs[(R + i) * LDP + c];
#pragma unroll
            for (int j = 0; j < 4; j++) kf[j] = Ks[(C4 + j) * LDP + c];
#pragma unroll
            for (int i = 0; i < 4; i++)
#pragma unroll
                for (int j = 0; j < 4; j++) s4[i][j] += qf[i] * kf[j];
        }
        // add decomposed rel-pos bias and stash in Ps
#pragma unroll
        for (int j = 0; j < 4; j++) {
            int mg = kt * 64 + C4 + j;
            int kh = mg / G;
            int kw = mg - kh * G;
#pragma unroll
            for (int i = 0; i < 4; i++)
                Ps[(R + i) * LDP + C4 + j] = s4[i][j] + rh[(R + i) * G + kh] + rw[(R + i) * G + kw];
        }
        __syncthreads();

        // online softmax: 4 threads per row
        {
            int r = tid >> 2, part = tid & 3;
            float* prow = Ps + r * LDP + part * 16;
            float mx = -1e30f;
#pragma unroll
            for (int j = 0; j < 16; j++) mx = fmaxf(mx, prow[j]);
            mx = fmaxf(mx, __shfl_xor_sync(0xffffffffu, mx, 1));
            mx = fmaxf(mx, __shfl_xor_sync(0xffffffffu, mx, 2));
            float mold = m_s[r];
            float mnew = fmaxf(mold, mx);
            float sum = 0.f;
#pragma unroll
            for (int j = 0; j < 16; j++) {
                float p = __expf(prow[j] - mnew);
                prow[j] = p;
                sum += p;
            }
            sum += __shfl_xor_sync(0xffffffffu, sum, 1);
            sum += __shfl_xor_sync(0xffffffffu, sum, 2);
            if (part == 0) {
                float alpha = __expf(mold - mnew);
                l_s[r] = l_s[r] * alpha + sum;
                m_s[r] = mnew;
                al_s[r] = alpha;
            }
        }
        __syncthreads();

        // rescale accumulators, then O += P * V
        float a[4];
#pragma unroll
        for (int i = 0; i < 4; i++) a[i] = al_s[R + i];
#pragma unroll
        for (int i = 0; i < 4; i++)
#pragma unroll
            for (int j = 0; j < 4; j++) acc[i][j] *= a[i];
#pragma unroll 16
        for (int mm = 0; mm < 64; mm++) {
            float pf[4], vf[4];
#pragma unroll
            for (int i = 0; i < 4; i++) pf[i] = Ps[(R + i) * LDP + mm];
#pragma unroll
            for (int j = 0; j < 4; j++) vf[j] = Vs[mm * LDP + C4 + j];
#pragma unroll
            for (int i = 0; i < 4; i++)
#pragma unroll
                for (int j = 0; j < 4; j++) acc[i][j] += pf[i] * vf[j];
        }
    }

    // epilogue: divide by l, write (token-major, head-interleaved) for proj GEMM
#pragma unroll
    for (int i = 0; i < 4; i++) {
        float inv = 1.f / l_s[R + i];
        int n = tile * 64 + R + i;
#pragma unroll
        for (int j = 0; j < 4; j++)
            g_ao[n * DIM + head * HD + C4 + j] = acc[i][j] * inv;
    }
}

// ---------------- launch ----------------------------------------------------
extern "C" void kernel_launch(void* const* d_in, const int* in_sizes, int n_in,
                              void* d_out, int out_size)
{
    const float* x   = (const float*)d_in[0];
    const float* Wq  = (const float*)d_in[1];
    const float* bq  = (const float*)d_in[2];
    const float* Wk  = (const float*)d_in[3];
    const float* bk  = (const float*)d_in[4];
    const float* Wv  = (const float*)d_in[5];
    const float* bv  = (const float*)d_in[6];
    const float* Wp  = (const float*)d_in[7];
    const float* bp  = (const float*)d_in[8];
    const float* rph = (const float*)d_in[9];
    const float* rpw = (const float*)d_in[10];
    const float* Aq  = (const float*)d_in[11];
    const float* Bq  = (const float*)d_in[12];
    const float* Ak  = (const float*)d_in[13];
    const float* Bk  = (const float*)d_in[14];
    const float* Av  = (const float*)d_in[15];
    const float* Bv  = (const float*)d_in[16];
    float* out = (float*)d_out;

    const int smem_bytes = (4 * 64 * LDP + 2 * 64 * G + 3 * 64) * (int)sizeof(float);
    cudaFuncSetAttribute(flash_kernel, cudaFuncAttributeMaxDynamicSharedMemorySize, smem_bytes);

    fuse_w<<<(3 * DIM * DIM + 255) / 256, 256>>>(Wq, Aq, Bq, Wk, Ak, Bk, Wv, Av, Bv);
    gemm_qkv<<<dim3(6, 18, 3), 256>>>(x, bq, bk, bv);
    rel_kernel<<<dim3(NTOK, HEADS), 128>>>(rph, rpw);
    flash_kernel<<<dim3(NT, HEADS), 256, smem_bytes>>>();
    gemm_proj<<<dim3(6, 18), 256>>>(Wp, bp, out);
}

// round 2
// speedup vs baseline: 1.5451x; 1.5451x over previous
#include <cuda_runtime.h>

#define DIM 768
#define HEADS 12
#define HD 64
#define G 48
#define NTOK 2304   // G*G
#define RANK 8
#define NKT 36      // 2304/64 k-tiles
#define QT 18       // 2304/128 q-tiles

// ---------------- scratch (device globals; no allocation allowed) ----------
__device__ __align__(16) float g_Wq[DIM*DIM];   // fused+transposed [n][k]
__device__ __align__(16) float g_Wk[DIM*DIM];
__device__ __align__(16) float g_Wv[DIM*DIM];
__device__ __align__(16) float g_Wp[DIM*DIM];   // transposed [n][k]
__device__ __align__(16) float g_q[HEADS*NTOK*HD];
__device__ __align__(16) float g_k[HEADS*NTOK*HD];
__device__ __align__(16) float g_v[HEADS*NTOK*HD];
__device__ __align__(16) float g_relh[HEADS*NTOK*G];
__device__ __align__(16) float g_relw[HEADS*NTOK*G];
__device__ __align__(16) float g_ao[NTOK*DIM];

// ---------------- tf32 helpers --------------------------------------------
__device__ __forceinline__ float tf32r(float f) {
    unsigned u; asm("cvt.rna.tf32.f32 %0, %1;" : "=r"(u) : "f"(f));
    return __uint_as_float(u);
}
__device__ __forceinline__ void mma8(float* d,
                                     float a0, float a1, float a2, float a3,
                                     float b0, float b1) {
    unsigned ua0 = __float_as_uint(a0), ua1 = __float_as_uint(a1);
    unsigned ua2 = __float_as_uint(a2), ua3 = __float_as_uint(a3);
    unsigned ub0 = __float_as_uint(b0), ub1 = __float_as_uint(b1);
    asm volatile("mma.sync.aligned.m16n8k8.row.col.f32.tf32.tf32.f32 "
                 "{%0,%1,%2,%3},{%4,%5,%6,%7},{%8,%9},{%0,%1,%2,%3};"
                 : "+f"(d[0]), "+f"(d[1]), "+f"(d[2]), "+f"(d[3])
                 : "r"(ua0), "r"(ua1), "r"(ua2), "r"(ua3), "r"(ub0), "r"(ub1));
}

// ---------------- kernel 1: fuse LoRA + transpose weights -> [n][k] --------
__global__ __launch_bounds__(256) void fuse_wt(
    const float* __restrict__ Wq, const float* __restrict__ Aq, const float* __restrict__ Bq,
    const float* __restrict__ Wk, const float* __restrict__ Ak, const float* __restrict__ Bk,
    const float* __restrict__ Wv, const float* __restrict__ Av, const float* __restrict__ Bv,
    const float* __restrict__ Wp)
{
    __shared__ float tb[32][33];
    int z = blockIdx.z;
    const float *W, *A = nullptr, *B = nullptr;
    float* O;
    if (z == 0)      { W = Wq; A = Aq; B = Bq; O = g_Wq; }
    else if (z == 1) { W = Wk; A = Ak; B = Bk; O = g_Wk; }
    else if (z == 2) { W = Wv; A = Av; B = Bv; O = g_Wv; }
    else             { W = Wp;                 O = g_Wp; }
    int kb = blockIdx.y * 32, nb = blockIdx.x * 32;
    int tx = threadIdx.x & 31, ty = threadIdx.x >> 5;   // 32 x 8
#pragma unroll
    for (int s = 0; s < 4; s++)
        tb[ty + 8 * s][tx] = W[(kb + ty + 8 * s) * DIM + nb + tx];
    __syncthreads();
#pragma unroll
    for (int s = 0; s < 4; s++) {
        int n = nb + ty + 8 * s;
        int k = kb + tx;
        float v = tb[tx][ty + 8 * s];
        if (z < 3) {
#pragma unroll
            for (int r = 0; r < RANK; r++)
                v += A[k * RANK + r] * B[r * DIM + n];
        }
        O[n * DIM + k] = v;
    }
}

// ---------------- tf32 GEMM engine: C[2304x768] = X[2304x768] * W^T --------
// CTA tile 128m x 128n, k-chunk 32. 8 warps as 4(m) x 2(n); warp = 32m x 64n.
#define LDA 36
__device__ __forceinline__ void gemm_engine(const float* __restrict__ Ain,
                                            const float* __restrict__ Bt,   // [n][k]
                                            const float* __restrict__ bias,
                                            float* __restrict__ outp,
                                            int head_major)
{
    __shared__ float As[128 * LDA];
    __shared__ float Bs[128 * LDA];
    int tid = threadIdx.x;
    int w = tid >> 5, l = tid & 31, g = l >> 2, t = l & 3;
    int wm = w >> 1, wn = w & 1;
    int m0 = blockIdx.y * 128;
    int n0 = blockIdx.x * 128;

    float acc[2][8][4];
#pragma unroll
    for (int i = 0; i < 2; i++)
#pragma unroll
        for (int j = 0; j < 8; j++)
#pragma unroll
            for (int e = 0; e < 4; e++) acc[i][j][e] = 0.f;

    for (int k0 = 0; k0 < DIM; k0 += 32) {
#pragma unroll
        for (int s = 0; s < 4; s++) {
            int id4 = tid + s * 256;              // 1024 float4 = 128 x 32
            int r = id4 >> 3, kc = (id4 & 7) * 4;
            float4 vv = *(const float4*)(Ain + (m0 + r) * DIM + k0 + kc);
            float* dst = &As[r * LDA + kc];
            dst[0] = tf32r(vv.x); dst[1] = tf32r(vv.y);
            dst[2] = tf32r(vv.z); dst[3] = tf32r(vv.w);
        }
#pragma unroll
        for (int s = 0; s < 4; s++) {
            int id4 = tid + s * 256;
            int n = id4 >> 3, kc = (id4 & 7) * 4;
            float4 vv = *(const float4*)(Bt + (n0 + n) * DIM + k0 + kc);
            float* dst = &Bs[n * LDA + kc];
            dst[0] = tf32r(vv.x); dst[1] = tf32r(vv.y);
            dst[2] = tf32r(vv.z); dst[3] = tf32r(vv.w);
        }
        __syncthreads();
#pragma unroll
        for (int ks = 0; ks < 4; ks++) {
            int kb = ks * 8;
            float a[2][4];
#pragma unroll
            for (int i = 0; i < 2; i++) {
                int r = wm * 32 + i * 16;
                a[i][0] = As[(r + g) * LDA + kb + t];
                a[i][1] = As[(r + g + 8) * LDA + kb + t];
                a[i][2] = As[(r + g) * LDA + kb + t + 4];
                a[i][3] = As[(r + g + 8) * LDA + kb + t + 4];
            }
#pragma unroll
            for (int j = 0; j < 8; j++) {
                int n = wn * 64 + j * 8;
                float b0 = Bs[(n + g) * LDA + kb + t];
                float b1 = Bs[(n + g) * LDA + kb + t + 4];
                mma8(acc[0][j], a[0][0], a[0][1], a[0][2], a[0][3], b0, b1);
                mma8(acc[1][j], a[1][0], a[1][1], a[1][2], a[1][3], b0, b1);
            }
        }
        __syncthreads();
    }
    // epilogue
#pragma unroll
    for (int i = 0; i < 2; i++) {
        int rbase = m0 + wm * 32 + i * 16 + g;
#pragma unroll
        for (int j = 0; j < 8; j++) {
            int c0 = n0 + wn * 64 + j * 8 + t * 2;
#pragma unroll
            for (int e = 0; e < 4; e++) {
                int r = rbase + ((e >= 2) ? 8 : 0);
                int c = c0 + (e & 1);
                float val = acc[i][j][e] + bias[c];
                if (head_major) {
                    int h = c >> 6, cc = c & 63;
                    outp[h * (NTOK * HD) + r * HD + cc] = val;
                } else {
                    outp[r * DIM + c] = val;
                }
            }
        }
    }
}

__global__ __launch_bounds__(256) void gemm_qkv(
    const float* __restrict__ x,
    const float* __restrict__ bq, const float* __restrict__ bk, const float* __restrict__ bv)
{
    int z = blockIdx.z;
    const float* W    = (z == 0) ? g_Wq : (z == 1) ? g_Wk : g_Wv;
    const float* bias = (z == 0) ? bq   : (z == 1) ? bk   : bv;
    float* outp       = (z == 0) ? g_q  : (z == 1) ? g_k  : g_v;
    gemm_engine(x, W, bias, outp, 1);
}

__global__ __launch_bounds__(256) void gemm_proj(
    const float* __restrict__ bp, float* __restrict__ out)
{
    gemm_engine(g_ao, g_Wp, bp, out, 0);
}

// ---------------- kernel 3: rel-pos dot tables -----------------------------
__global__ __launch_bounds__(128) void rel_kernel(
    const float* __restrict__ rph, const float* __restrict__ rpw)
{
    int n = blockIdx.x;
    int head = blockIdx.y;
    __shared__ float qs[HD];
    int tid = threadIdx.x;
    if (tid < HD) qs[tid] = g_q[head * (NTOK * HD) + n * HD + tid];
    __syncthreads();
    int hq = n / G;
    int wq = n - hq * G;
    if (tid < G) {
        const float* row = rph + (hq - tid + G - 1) * HD;
        float s = 0.f;
#pragma unroll 16
        for (int c = 0; c < HD; c++) s += qs[c] * row[c];
        g_relh[(head * NTOK + n) * G + tid] = s;
    } else if (tid >= 64 && tid < 64 + G) {
        int kw = tid - 64;
        const float* row = rpw + (wq - kw + G - 1) * HD;
        float s = 0.f;
#pragma unroll 16
        for (int c = 0; c < HD; c++) s += qs[c] * row[c];
        g_relw[(head * NTOK + n) * G + kw] = s;
    }
}

// ---------------- kernel 4: tf32 tensor-core flash attention ---------------
// CTA: 128 q-rows x all keys, k-tile 64. 8 warps; warp w owns q-rows 16w..16w+15.
#define LKS 68   // K tile stride  (mod 32 == 4 -> conflict-free B-frags)
#define LVS 72   // V tile stride  (mod 32 == 8 -> conflict-free B-frags)
#define LPS 68   // P / Q-stage stride
__global__ __launch_bounds__(256) void flash2()
{
    extern __shared__ float sm[];
    float* Ks = sm;                 // 64*LKS
    float* Vs = Ks + 64 * LKS;      // 64*LVS
    float* Ps = Vs + 64 * LVS;      // 128*LPS (Q staging, then P)

    int tile = blockIdx.x, head = blockIdx.y;
    int tid = threadIdx.x, w = tid >> 5, l = tid & 31, g = l >> 2, t = l & 3;

    // ---- stage Q (pre-scaled, tf32) ----
    const float* qb = g_q + head * (NTOK * HD) + tile * 128 * HD;
#pragma unroll
    for (int s = 0; s < 8; s++) {
        int id4 = tid + s * 256;            // 2048 float4 = 128 x 64
        int r = id4 >> 4, c4 = (id4 & 15) * 4;
        float4 vv = *(const float4*)(qb + id4 * 4);
        float* dst = &Ps[r * LPS + c4];
        dst[0] = tf32r(vv.x * 0.125f); dst[1] = tf32r(vv.y * 0.125f);
        dst[2] = tf32r(vv.z * 0.125f); dst[3] = tf32r(vv.w * 0.125f);
    }
    __syncthreads();

    // ---- Q fragments in registers (8 k-steps x 4 regs) ----
    float qf[8][4];
    {
        int r = w * 16;
#pragma unroll
        for (int ks = 0; ks < 8; ks++) {
            qf[ks][0] = Ps[(r + g) * LPS + ks * 8 + t];
            qf[ks][1] = Ps[(r + g + 8) * LPS + ks * 8 + t];
            qf[ks][2] = Ps[(r + g) * LPS + ks * 8 + t + 4];
            qf[ks][3] = Ps[(r + g + 8) * LPS + ks * 8 + t + 4];
        }
    }

    int rg0 = tile * 128 + w * 16 + g;      // global q row of C-frag elems 0,1
    const float* rhb = g_relh + head * NTOK * G;
    const float* rwb = g_relw + head * NTOK * G;
    const float* kbase = g_k + head * (NTOK * HD);
    const float* vbase = g_v + head * (NTOK * HD);

    float o[8][4];
#pragma unroll
    for (int j = 0; j < 8; j++)
#pragma unroll
        for (int e = 0; e < 4; e++) o[j][e] = 0.f;
    float m0 = -1e30f, m1 = -1e30f, l0 = 0.f, l1 = 0.f;

    for (int kt = 0; kt < NKT; kt++) {
        __syncthreads();
        // ---- load K, V tiles (tf32) ----
#pragma unroll
        for (int s = 0; s < 4; s++) {
            int id4 = tid + s * 256;        // 1024 float4 = 64 x 64
            int r = id4 >> 4, c4 = (id4 & 15) * 4;
            float4 kv = *(const float4*)(kbase + kt * 64 * HD + id4 * 4);
            float* kd = &Ks[r * LKS + c4];
            kd[0] = tf32r(kv.x); kd[1] = tf32r(kv.y);
            kd[2] = tf32r(kv.z); kd[3] = tf32r(kv.w);
            float4 vv = *(const float4*)(vbase + kt * 64 * HD + id4 * 4);
            float* vd = &Vs[r * LVS + c4];
            vd[0] = tf32r(vv.x); vd[1] = tf32r(vv.y);
            vd[2] = tf32r(vv.z); vd[3] = tf32r(vv.w);
        }
        __syncthreads();

        // ---- S = Q K^T ----
        float s4[8][4];
#pragma unroll
        for (int j = 0; j < 8; j++)
#pragma unroll
            for (int e = 0; e < 4; e++) s4[j][e] = 0.f;
#pragma unroll
        for (int ks = 0; ks < 8; ks++) {
#pragma unroll
            for (int j = 0; j < 8; j++) {
                float b0 = Ks[(j * 8 + g) * LKS + ks * 8 + t];
                float b1 = Ks[(j * 8 + g) * LKS + ks * 8 + t + 4];
                mma8(s4[j], qf[ks][0], qf[ks][1], qf[ks][2], qf[ks][3], b0, b1);
            }
        }

        // ---- decomposed rel-pos bias ----
        int colbase = kt * 64;
        int khA = colbase / G;
        int khB = (colbase + 63) / G;
        float rhA0 = rhb[rg0 * G + khA],       rhB0 = rhb[rg0 * G + khB];
        float rhA1 = rhb[(rg0 + 8) * G + khA], rhB1 = rhb[(rg0 + 8) * G + khB];
#pragma unroll
        for (int j = 0; j < 8; j++) {
            int c0 = colbase + j * 8 + t * 2;
            int c1 = c0 + 1;
            int kh0 = c0 / G, kw0 = c0 - kh0 * G;
            int kh1 = c1 / G, kw1 = c1 - kh1 * G;
            s4[j][0] += ((kh0 == khA) ? rhA0 : rhB0) + rwb[rg0 * G + kw0];
            s4[j][1] += ((kh1 == khA) ? rhA0 : rhB0) + rwb[rg0 * G + kw1];
            s4[j][2] += ((kh0 == khA) ? rhA1 : rhB1) + rwb[(rg0 + 8) * G + kw0];
            s4[j][3] += ((kh1 == khA) ? rhA1 : rhB1) + rwb[(rg0 + 8) * G + kw1];
        }

        // ---- online softmax (registers + shfl across the 4-lane group) ----
        float mx0 = -1e30f, mx1 = -1e30f;
#pragma unroll
        for (int j = 0; j < 8; j++) {
            mx0 = fmaxf(mx0, fmaxf(s4[j][0], s4[j][1]));
            mx1 = fmaxf(mx1, fmaxf(s4[j][2], s4[j][3]));
        }
        mx0 = fmaxf(mx0, __shfl_xor_sync(0xffffffffu, mx0, 1));
        mx0 = fmaxf(mx0, __shfl_xor_sync(0xffffffffu, mx0, 2));
        mx1 = fmaxf(mx1, __shfl_xor_sync(0xffffffffu, mx1, 1));
        mx1 = fmaxf(mx1, __shfl_xor_sync(0xffffffffu, mx1, 2));
        float mn0 = fmaxf(m0, mx0), mn1 = fmaxf(m1, mx1);
        float sum0 = 0.f, sum1 = 0.f;
#pragma unroll
        for (int j = 0; j < 8; j++) {
            s4[j][0] = __expf(s4[j][0] - mn0);
            s4[j][1] = __expf(s4[j][1] - mn0);
            s4[j][2] = __expf(s4[j][2] - mn1);
            s4[j][3] = __expf(s4[j][3] - mn1);
            sum0 += s4[j][0] + s4[j][1];
            sum1 += s4[j][2] + s4[j][3];
        }
        sum0 += __shfl_xor_sync(0xffffffffu, sum0, 1);
        sum0 += __shfl_xor_sync(0xffffffffu, sum0, 2);
        sum1 += __shfl_xor_sync(0xffffffffu, sum1, 1);
        sum1 += __shfl_xor_sync(0xffffffffu, sum1, 2);
        float al0 = __expf(m0 - mn0), al1 = __expf(m1 - mn1);
        l0 = l0 * al0 + sum0;  l1 = l1 * al1 + sum1;
        m0 = mn0;  m1 = mn1;
#pragma unroll
        for (int j = 0; j < 8; j++) {
            o[j][0] *= al0; o[j][1] *= al0;
            o[j][2] *= al1; o[j][3] *= al1;
        }

        // ---- write P (tf32) to warp-private rows of Ps ----
        int pr = w * 16;
#pragma unroll
        for (int j = 0; j < 8; j++) {
            int mc = j * 8 + t * 2;
            Ps[(pr + g) * LPS + mc]         = tf32r(s4[j][0]);
            Ps[(pr + g) * LPS + mc + 1]     = tf32r(s4[j][1]);
            Ps[(pr + g + 8) * LPS + mc]     = tf32r(s4[j][2]);
            Ps[(pr + g + 8) * LPS + mc + 1] = tf32r(s4[j][3]);
        }
        __syncwarp();

        // ---- O += P V ----
#pragma unroll
        for (int ms = 0; ms < 8; ms++) {
            float a0 = Ps[(pr + g) * LPS + ms * 8 + t];
            float a1 = Ps[(pr + g + 8) * LPS + ms * 8 + t];
            float a2 = Ps[(pr + g) * LPS + ms * 8 + t + 4];
            float a3 = Ps[(pr + g + 8) * LPS + ms * 8 + t + 4];
#pragma unroll
            for (int j = 0; j < 8; j++) {
                float b0 = Vs[(ms * 8 + t) * LVS + j * 8 + g];
                float b1 = Vs[(ms * 8 + t + 4) * LVS + j * 8 + g];
                mma8(o[j], a0, a1, a2, a3, b0, b1);
            }
        }
        __syncwarp();
    }

    // ---- epilogue ----
    float inv0 = 1.f / l0, inv1 = 1.f / l1;
    int nq0 = tile * 128 + w * 16 + g;
#pragma unroll
    for (int j = 0; j < 8; j++) {
        int c = head * HD + j * 8 + t * 2;
        g_ao[nq0 * DIM + c]           = o[j][0] * inv0;
        g_ao[nq0 * DIM + c + 1]       = o[j][1] * inv0;
        g_ao[(nq0 + 8) * DIM + c]     = o[j][2] * inv1;
        g_ao[(nq0 + 8) * DIM + c + 1] = o[j][3] * inv1;
    }
}

// ---------------- launch ----------------------------------------------------
extern "C" void kernel_launch(void* const* d_in, const int* in_sizes, int n_in,
                              void* d_out, int out_size)
{
    const float* x   = (const float*)d_in[0];
    const float* Wq  = (const float*)d_in[1];
    const float* bq  = (const float*)d_in[2];
    const float* Wk  = (const float*)d_in[3];
    const float* bk  = (const float*)d_in[4];
    const float* Wv  = (const float*)d_in[5];
    const float* bv  = (const float*)d_in[6];
    const float* Wp  = (const float*)d_in[7];
    const float* bp  = (const float*)d_in[8];
    const float* rph = (const float*)d_in[9];
    const float* rpw = (const float*)d_in[10];
    const float* Aq  = (const float*)d_in[11];
    const float* Bq  = (const float*)d_in[12];
    const float* Ak  = (const float*)d_in[13];
    const float* Bk  = (const float*)d_in[14];
    const float* Av  = (const float*)d_in[15];
    const float* Bv  = (const float*)d_in[16];
    float* out = (float*)d_out;

    const int smem_bytes = (64 * LKS + 64 * LVS + 128 * LPS) * (int)sizeof(float);
    cudaFuncSetAttribute(flash2, cudaFuncAttributeMaxDynamicSharedMemorySize, smem_bytes);

    fuse_wt<<<dim3(24, 24, 4), 256>>>(Wq, Aq, Bq, Wk, Ak, Bk, Wv, Av, Bv, Wp);
    gemm_qkv<<<dim3(6, 18, 3), 256>>>(x, bq, bk, bv);
    rel_kernel<<<dim3(NTOK, HEADS), 128>>>(rph, rpw);
    flash2<<<dim3(QT, HEADS), 256, smem_bytes>>>();
    gemm_proj<<<dim3(6, 18), 256>>>(bp, out);
}

// round 3
// speedup vs baseline: 4.3127x; 2.7912x over previous
#include <cuda_runtime.h>
#include <cstdint>

#define DIM 768
#define HEADS 12
#define HD 64
#define G 48
#define NTOK 2304
#define RANK 8
#define NKT 36      // 2304/64 k-tiles

// ---------------- scratch --------------------------------------------------
__device__ __align__(16) float g_x[NTOK*DIM];          // tf32-rounded x
__device__ __align__(16) float g_Wqkv[3*DIM*DIM];      // fused+transposed+rounded [n][k]
__device__ __align__(16) float g_Wp[DIM*DIM];          // transposed+rounded [n][k]
__device__ __align__(16) float g_q[HEADS*NTOK*HD];     // tf32-rounded
__device__ __align__(16) float g_k[HEADS*NTOK*HD];
__device__ __align__(16) float g_v[HEADS*NTOK*HD];
__device__ __align__(16) float g_relh[HEADS*NTOK*G];
__device__ __align__(16) float g_relw[HEADS*NTOK*G];
__device__ __align__(16) float g_ao[NTOK*DIM];         // tf32-rounded

// ---------------- helpers ---------------------------------------------------
__device__ __forceinline__ float tf32r(float f) {
    unsigned u; asm("cvt.rna.tf32.f32 %0, %1;" : "=r"(u) : "f"(f));
    return __uint_as_float(u);
}
__device__ __forceinline__ void mma8(float* d,
                                     float a0, float a1, float a2, float a3,
                                     float b0, float b1) {
    unsigned ua0 = __float_as_uint(a0), ua1 = __float_as_uint(a1);
    unsigned ua2 = __float_as_uint(a2), ua3 = __float_as_uint(a3);
    unsigned ub0 = __float_as_uint(b0), ub1 = __float_as_uint(b1);
    asm volatile("mma.sync.aligned.m16n8k8.row.col.f32.tf32.tf32.f32 "
                 "{%0,%1,%2,%3},{%4,%5,%6,%7},{%8,%9},{%0,%1,%2,%3};"
                 : "+f"(d[0]), "+f"(d[1]), "+f"(d[2]), "+f"(d[3])
                 : "r"(ua0), "r"(ua1), "r"(ua2), "r"(ua3), "r"(ub0), "r"(ub1));
}
__device__ __forceinline__ void cpa16(uint32_t dst, const float* src) {
    asm volatile("cp.async.cg.shared.global [%0], [%1], 16;" :: "r"(dst), "l"(src));
}
#define CP_COMMIT() asm volatile("cp.async.commit_group;")
#define CP_WAIT(n)  asm volatile("cp.async.wait_group " #n ";")

// ---------------- kernel 0: round x to tf32 --------------------------------
__global__ __launch_bounds__(256) void round_x(const float* __restrict__ x) {
    int i = (blockIdx.x * 256 + threadIdx.x) * 4;
    float4 v = *(const float4*)(x + i);
    float4 o = make_float4(tf32r(v.x), tf32r(v.y), tf32r(v.z), tf32r(v.w));
    *(float4*)(g_x + i) = o;
}

// ---------------- kernel 1: fuse LoRA + transpose + round -------------------
__global__ __launch_bounds__(256) void fuse_wt(
    const float* __restrict__ Wq, const float* __restrict__ Aq, const float* __restrict__ Bq,
    const float* __restrict__ Wk, const float* __restrict__ Ak, const float* __restrict__ Bk,
    const float* __restrict__ Wv, const float* __restrict__ Av, const float* __restrict__ Bv,
    const float* __restrict__ Wp)
{
    __shared__ float tb[32][33];
    int z = blockIdx.z;
    const float *W, *A = nullptr, *B = nullptr;
    float* O;
    if (z == 0)      { W = Wq; A = Aq; B = Bq; O = g_Wqkv; }
    else if (z == 1) { W = Wk; A = Ak; B = Bk; O = g_Wqkv + DIM*DIM; }
    else if (z == 2) { W = Wv; A = Av; B = Bv; O = g_Wqkv + 2*DIM*DIM; }
    else             { W = Wp;                 O = g_Wp; }
    int kb = blockIdx.y * 32, nb = blockIdx.x * 32;
    int tx = threadIdx.x & 31, ty = threadIdx.x >> 5;   // 32 x 8
#pragma unroll
    for (int s = 0; s < 4; s++)
        tb[ty + 8 * s][tx] = W[(kb + ty + 8 * s) * DIM + nb + tx];
    __syncthreads();
#pragma unroll
    for (int s = 0; s < 4; s++) {
        int n = nb + ty + 8 * s;
        int k = kb + tx;
        float v = tb[tx][ty + 8 * s];
        if (z < 3) {
#pragma unroll
            for (int r = 0; r < RANK; r++)
                v += A[k * RANK + r] * B[r * DIM + n];
        }
        O[n * DIM + k] = tf32r(v);
    }
}

// ---------------- GEMM core: 128x128 tile, cp.async double-buffered k=32 ---
#define LDA 36
#define GBUF (128*LDA)
__device__ __forceinline__ void gemm_body(const float* __restrict__ Ain,   // row m0 base
                                          const float* __restrict__ Btn,   // row n0 base [n][k]
                                          float acc[2][8][4], float* sm)
{
    int tid = threadIdx.x;
    int w = tid >> 5, l = tid & 31, g = l >> 2, t = l & 3;
    int wm = w >> 1, wn = w & 1;
    float* AS0 = sm;            float* AS1 = sm + GBUF;
    float* BS0 = sm + 2*GBUF;   float* BS1 = sm + 3*GBUF;
    uint32_t as0 = (uint32_t)__cvta_generic_to_shared(AS0);
    uint32_t as1 = (uint32_t)__cvta_generic_to_shared(AS1);
    uint32_t bs0 = (uint32_t)__cvta_generic_to_shared(BS0);
    uint32_t bs1 = (uint32_t)__cvta_generic_to_shared(BS1);

    // prologue: chunk 0 into buf0
#pragma unroll
    for (int s = 0; s < 4; s++) {
        int id4 = tid + s * 256;
        int r = id4 >> 3, kc = (id4 & 7) * 4;
        cpa16(as0 + (r * LDA + kc) * 4, Ain + r * DIM + kc);
        cpa16(bs0 + (r * LDA + kc) * 4, Btn + r * DIM + kc);
    }
    CP_COMMIT();

    for (int c = 0; c < 24; c++) {
        int buf = c & 1;
        if (c < 23) {
            uint32_t ad = buf ? as0 : as1;
            uint32_t bd = buf ? bs0 : bs1;
            int k0 = (c + 1) * 32;
#pragma unroll
            for (int s = 0; s < 4; s++) {
                int id4 = tid + s * 256;
                int r = id4 >> 3, kc = (id4 & 7) * 4;
                cpa16(ad + (r * LDA + kc) * 4, Ain + r * DIM + k0 + kc);
                cpa16(bd + (r * LDA + kc) * 4, Btn + r * DIM + k0 + kc);
            }
            CP_COMMIT();
            CP_WAIT(1);
        } else {
            CP_WAIT(0);
        }
        __syncthreads();
        const float* As = buf ? AS1 : AS0;
        const float* Bs = buf ? BS1 : BS0;
#pragma unroll
        for (int ks = 0; ks < 4; ks++) {
            int kb = ks * 8;
            float a[2][4];
#pragma unroll
            for (int i = 0; i < 2; i++) {
                int r = wm * 32 + i * 16;
                a[i][0] = As[(r + g) * LDA + kb + t];
                a[i][1] = As[(r + g + 8) * LDA + kb + t];
                a[i][2] = As[(r + g) * LDA + kb + t + 4];
                a[i][3] = As[(r + g + 8) * LDA + kb + t + 4];
            }
#pragma unroll
            for (int j = 0; j < 8; j++) {
                int n = wn * 64 + j * 8;
                float b0 = Bs[(n + g) * LDA + kb + t];
                float b1 = Bs[(n + g) * LDA + kb + t + 4];
                mma8(acc[0][j], a[0][0], a[0][1], a[0][2], a[0][3], b0, b1);
                mma8(acc[1][j], a[1][0], a[1][1], a[1][2], a[1][3], b0, b1);
            }
        }
        __syncthreads();
    }
}

// ---------------- kernel 2: fused QKV GEMM ---------------------------------
__global__ __launch_bounds__(256, 2) void gemm_qkvf(
    const float* __restrict__ bq, const float* __restrict__ bk, const float* __restrict__ bv)
{
    extern __shared__ float sm[];
    int m0 = blockIdx.y * 128, n0 = blockIdx.x * 128;
    float acc[2][8][4];
#pragma unroll
    for (int i = 0; i < 2; i++)
#pragma unroll
        for (int j = 0; j < 8; j++)
#pragma unroll
            for (int e = 0; e < 4; e++) acc[i][j][e] = 0.f;
    gemm_body(g_x + m0 * DIM, g_Wqkv + n0 * DIM, acc, sm);

    int z = n0 / DIM;
    int nb = n0 - z * DIM;
    const float* bias = (z == 0) ? bq : (z == 1) ? bk : bv;
    float* outp       = (z == 0) ? g_q : (z == 1) ? g_k : g_v;
    int tid = threadIdx.x;
    int w = tid >> 5, l = tid & 31, g = l >> 2, t = l & 3;
    int wm = w >> 1, wn = w & 1;
#pragma unroll
    for (int i = 0; i < 2; i++) {
        int r0 = m0 + wm * 32 + i * 16 + g;
#pragma unroll
        for (int j = 0; j < 8; j++) {
            int c = nb + wn * 64 + j * 8 + t * 2;
            int h = c >> 6, cc = c & 63;
            float2 v0 = make_float2(tf32r(acc[i][j][0] + bias[c]),
                                    tf32r(acc[i][j][1] + bias[c + 1]));
            float2 v1 = make_float2(tf32r(acc[i][j][2] + bias[c]),
                                    tf32r(acc[i][j][3] + bias[c + 1]));
            *(float2*)&outp[h * (NTOK * HD) + r0 * HD + cc] = v0;
            *(float2*)&outp[h * (NTOK * HD) + (r0 + 8) * HD + cc] = v1;
        }
    }
}

// ---------------- kernel 5: output projection ------------------------------
__global__ __launch_bounds__(256, 2) void gemm_projf(
    const float* __restrict__ bp, float* __restrict__ out)
{
    extern __shared__ float sm[];
    int m0 = blockIdx.y * 128, n0 = blockIdx.x * 128;
    float acc[2][8][4];
#pragma unroll
    for (int i = 0; i < 2; i++)
#pragma unroll
        for (int j = 0; j < 8; j++)
#pragma unroll
            for (int e = 0; e < 4; e++) acc[i][j][e] = 0.f;
    gemm_body(g_ao + m0 * DIM, g_Wp + n0 * DIM, acc, sm);

    int tid = threadIdx.x;
    int w = tid >> 5, l = tid & 31, g = l >> 2, t = l & 3;
    int wm = w >> 1, wn = w & 1;
#pragma unroll
    for (int i = 0; i < 2; i++) {
        int r0 = m0 + wm * 32 + i * 16 + g;
#pragma unroll
        for (int j = 0; j < 8; j++) {
            int c = n0 + wn * 64 + j * 8 + t * 2;
            float2 v0 = make_float2(acc[i][j][0] + bp[c], acc[i][j][1] + bp[c + 1]);
            float2 v1 = make_float2(acc[i][j][2] + bp[c], acc[i][j][3] + bp[c + 1]);
            *(float2*)&out[r0 * DIM + c] = v0;
            *(float2*)&out[(r0 + 8) * DIM + c] = v1;
        }
    }
}

// ---------------- kernel 3: rel-pos dot tables (smem tiled) -----------------
__global__ __launch_bounds__(256) void rel2(
    const float* __restrict__ rph, const float* __restrict__ rpw)
{
    __shared__ float qs[48 * 65];
    __shared__ float rp[48 * 65];
    int head = blockIdx.x;     // 0..11
    int p    = blockIdx.y;     // 0..47 (hq for z=0, wq for z=1)
    int z    = blockIdx.z;     // 0: relh, 1: relw
    int tid  = threadIdx.x;
    const float* qhead = g_q + head * (NTOK * HD);
    const float* rpsrc = (z == 0) ? rph : rpw;

#pragma unroll
    for (int s = 0; s < 3; s++) {
        int id4 = tid + s * 256;          // 768 float4 = 48 x 64
        int r = id4 >> 4, c = (id4 & 15) * 4;
        int n = (z == 0) ? (p * G + r) : (r * G + p);
        float4 qv = *(const float4*)(qhead + n * HD + c);
        float* qd = &qs[r * 65 + c];
        qd[0] = qv.x; qd[1] = qv.y; qd[2] = qv.z; qd[3] = qv.w;
        float4 rv = *(const float4*)(rpsrc + (p + r) * HD + c);
        float* rd = &rp[r * 65 + c];
        rd[0] = rv.x; rd[1] = rv.y; rd[2] = rv.z; rd[3] = rv.w;
    }
    __syncthreads();

#pragma unroll
    for (int s = 0; s < 9; s++) {
        int idx = tid + s * 256;          // 2304 = 48 x 48
        int i = idx / G;                  // row within 48
        int j = idx - i * G;              // kh / kw
        int d = (G - 1) - j;
        float acc = 0.f;
        const float* qr = &qs[i * 65];
        const float* rr = &rp[d * 65];
#pragma unroll 16
        for (int c = 0; c < HD; c++) acc += qr[c] * rr[c];
        int n = (z == 0) ? (p * G + i) : (i * G + p);
        float* dst = (z == 0) ? g_relh : g_relw;
        dst[(head * NTOK + n) * G + j] = acc;
    }
}

// ---------------- kernel 4: flash attention (cp.async pipelined) -----------
#define LKS 68
#define LVS 72
#define LPS 68
__global__ __launch_bounds__(128, 3) void flash3()
{
    extern __shared__ float sm[];
    float* Kb0 = sm;
    float* Kb1 = Kb0 + 64 * LKS;
    float* Vs  = Kb1 + 64 * LKS;
    float* Ps  = Vs + 64 * LVS;
    uint32_t kb0a = (uint32_t)__cvta_generic_to_shared(Kb0);
    uint32_t kb1a = (uint32_t)__cvta_generic_to_shared(Kb1);
    uint32_t vsa  = (uint32_t)__cvta_generic_to_shared(Vs);

    int tile = blockIdx.x, head = blockIdx.y;
    int tid = threadIdx.x, w = tid >> 5, l = tid & 31, g = l >> 2, t = l & 3;
    const float* qb    = g_q + head * (NTOK * HD) + tile * 64 * HD;
    const float* kbase = g_k + head * (NTOK * HD);
    const float* vbase = g_v + head * (NTOK * HD);

    // stage Q (x 0.125, exact power of two: stays tf32)
#pragma unroll
    for (int s = 0; s < 8; s++) {
        int id4 = tid + s * 128;
        int r = id4 >> 4, c = (id4 & 15) * 4;
        float4 v = *(const float4*)(qb + id4 * 4);
        float4 o = make_float4(v.x * 0.125f, v.y * 0.125f, v.z * 0.125f, v.w * 0.125f);
        *(float4*)&Ps[r * LPS + c] = o;
    }
    // issue K(0)
#pragma unroll
    for (int s = 0; s < 8; s++) {
        int id4 = tid + s * 128;
        int r = id4 >> 4, c = (id4 & 15) * 4;
        cpa16(kb0a + (r * LKS + c) * 4, kbase + id4 * 4);
    }
    CP_COMMIT();
    __syncthreads();

    // Q fragments
    float qf[8][4];
    int pr = w * 16;
#pragma unroll
    for (int ks = 0; ks < 8; ks++) {
        qf[ks][0] = Ps[(pr + g) * LPS + ks * 8 + t];
        qf[ks][1] = Ps[(pr + g + 8) * LPS + ks * 8 + t];
        qf[ks][2] = Ps[(pr + g) * LPS + ks * 8 + t + 4];
        qf[ks][3] = Ps[(pr + g + 8) * LPS + ks * 8 + t + 4];
    }

    int rg0 = tile * 64 + w * 16 + g;
    const float* rhb = g_relh + head * NTOK * G;
    const float* rwb = g_relw + head * NTOK * G;

    float o[8][4];
#pragma unroll
    for (int j = 0; j < 8; j++)
#pragma unroll
        for (int e = 0; e < 4; e++) o[j][e] = 0.f;
    float m0v = -1e30f, m1v = -1e30f, l0 = 0.f, l1 = 0.f;

    for (int kt = 0; kt < NKT; kt++) {
        const float* Ks = (kt & 1) ? Kb1 : Kb0;
        // issue K(kt+1) into the other buffer
        if (kt + 1 < NKT) {
            uint32_t dst = (kt & 1) ? kb0a : kb1a;
            const float* src = kbase + (kt + 1) * 64 * HD;
#pragma unroll
            for (int s = 0; s < 8; s++) {
                int id4 = tid + s * 128;
                int r = id4 >> 4, c = (id4 & 15) * 4;
                cpa16(dst + (r * LKS + c) * 4, src + id4 * 4);
            }
            CP_COMMIT();
        }
        // issue V(kt)
        {
            const float* src = vbase + kt * 64 * HD;
#pragma unroll
            for (int s = 0; s < 8; s++) {
                int id4 = tid + s * 128;
                int r = id4 >> 4, c = (id4 & 15) * 4;
                cpa16(vsa + (r * LVS + c) * 4, src + id4 * 4);
            }
            CP_COMMIT();
        }
        if (kt + 1 < NKT) { CP_WAIT(2); } else { CP_WAIT(1); }   // K(kt) ready
        __syncthreads();

        // S = Q K^T
        float s4[8][4];
#pragma unroll
        for (int j = 0; j < 8; j++)
#pragma unroll
            for (int e = 0; e < 4; e++) s4[j][e] = 0.f;
#pragma unroll
        for (int ks = 0; ks < 8; ks++) {
#pragma unroll
            for (int j = 0; j < 8; j++) {
                float b0 = Ks[(j * 8 + g) * LKS + ks * 8 + t];
                float b1 = Ks[(j * 8 + g) * LKS + ks * 8 + t + 4];
                mma8(s4[j], qf[ks][0], qf[ks][1], qf[ks][2], qf[ks][3], b0, b1);
            }
        }

        // decomposed rel-pos bias
        int colbase = kt * 64;
        int khA = colbase / G;
        int khB = (colbase + 63) / G;
        float rhA0 = rhb[rg0 * G + khA],       rhB0 = rhb[rg0 * G + khB];
        float rhA1 = rhb[(rg0 + 8) * G + khA], rhB1 = rhb[(rg0 + 8) * G + khB];
#pragma unroll
        for (int j = 0; j < 8; j++) {
            int c0 = colbase + j * 8 + t * 2;
            int c1 = c0 + 1;
            int kh0 = c0 / G, kw0 = c0 - kh0 * G;
            int kh1 = c1 / G, kw1 = c1 - kh1 * G;
            s4[j][0] += ((kh0 == khA) ? rhA0 : rhB0) + rwb[rg0 * G + kw0];
            s4[j][1] += ((kh1 == khA) ? rhA0 : rhB0) + rwb[rg0 * G + kw1];
            s4[j][2] += ((kh0 == khA) ? rhA1 : rhB1) + rwb[(rg0 + 8) * G + kw0];
            s4[j][3] += ((kh1 == khA) ? rhA1 : rhB1) + rwb[(rg0 + 8) * G + kw1];
        }

        // online softmax
        float mx0 = -1e30f, mx1 = -1e30f;
#pragma unroll
        for (int j = 0; j < 8; j++) {
            mx0 = fmaxf(mx0, fmaxf(s4[j][0], s4[j][1]));
            mx1 = fmaxf(mx1, fmaxf(s4[j][2], s4[j][3]));
        }
        mx0 = fmaxf(mx0, __shfl_xor_sync(0xffffffffu, mx0, 1));
        mx0 = fmaxf(mx0, __shfl_xor_sync(0xffffffffu, mx0, 2));
        mx1 = fmaxf(mx1, __shfl_xor_sync(0xffffffffu, mx1, 1));
        mx1 = fmaxf(mx1, __shfl_xor_sync(0xffffffffu, mx1, 2));
        float mn0 = fmaxf(m0v, mx0), mn1 = fmaxf(m1v, mx1);
        float sum0 = 0.f, sum1 = 0.f;
#pragma unroll
        for (int j = 0; j < 8; j++) {
            s4[j][0] = __expf(s4[j][0] - mn0);
            s4[j][1] = __expf(s4[j][1] - mn0);
            s4[j][2] = __expf(s4[j][2] - mn1);
            s4[j][3] = __expf(s4[j][3] - mn1);
            sum0 += s4[j][0] + s4[j][1];
            sum1 += s4[j][2] + s4[j][3];
        }
        sum0 += __shfl_xor_sync(0xffffffffu, sum0, 1);
        sum0 += __shfl_xor_sync(0xffffffffu, sum0, 2);
        sum1 += __shfl_xor_sync(0xffffffffu, sum1, 1);
        sum1 += __shfl_xor_sync(0xffffffffu, sum1, 2);
        float al0 = __expf(m0v - mn0), al1 = __expf(m1v - mn1);
        l0 = l0 * al0 + sum0;  l1 = l1 * al1 + sum1;
        m0v = mn0;  m1v = mn1;
#pragma unroll
        for (int j = 0; j < 8; j++) {
            o[j][0] *= al0; o[j][1] *= al0;
            o[j][2] *= al1; o[j][3] *= al1;
        }

        // write P (tf32) to warp-private rows of Ps
#pragma unroll
        for (int j = 0; j < 8; j++) {
            int mc = j * 8 + t * 2;
            Ps[(pr + g) * LPS + mc]         = tf32r(s4[j][0]);
            Ps[(pr + g) * LPS + mc + 1]     = tf32r(s4[j][1]);
            Ps[(pr + g + 8) * LPS + mc]     = tf32r(s4[j][2]);
            Ps[(pr + g + 8) * LPS + mc + 1] = tf32r(s4[j][3]);
        }
        if (kt + 1 < NKT) { CP_WAIT(1); } else { CP_WAIT(0); }   // V(kt) ready
        __syncthreads();

        // O += P V
#pragma unroll
        for (int ms = 0; ms < 8; ms++) {
            float a0 = Ps[(pr + g) * LPS + ms * 8 + t];
            float a1 = Ps[(pr + g + 8) * LPS + ms * 8 + t];
            float a2 = Ps[(pr + g) * LPS + ms * 8 + t + 4];
            float a3 = Ps[(pr + g + 8) * LPS + ms * 8 + t + 4];
#pragma unroll
            for (int j = 0; j < 8; j++) {
                float b0 = Vs[(ms * 8 + t) * LVS + j * 8 + g];
                float b1 = Vs[(ms * 8 + t + 4) * LVS + j * 8 + g];
                mma8(o[j], a0, a1, a2, a3, b0, b1);
            }
        }
        __syncthreads();   // Vs / Kb[kt&1] free for next iteration's issues
    }

    // epilogue (tf32-rounded for the projection GEMM)
    float inv0 = 1.f / l0, inv1 = 1.f / l1;
    int nq0 = tile * 64 + w * 16 + g;
#pragma unroll
    for (int j = 0; j < 8; j++) {
        int c = head * HD + j * 8 + t * 2;
        float2 v0 = make_float2(tf32r(o[j][0] * inv0), tf32r(o[j][1] * inv0));
        float2 v1 = make_float2(tf32r(o[j][2] * inv1), tf32r(o[j][3] * inv1));
        *(float2*)&g_ao[nq0 * DIM + c] = v0;
        *(float2*)&g_ao[(nq0 + 8) * DIM + c] = v1;
    }
}

// ---------------- launch ----------------------------------------------------
extern "C" void kernel_launch(void* const* d_in, const int* in_sizes, int n_in,
                              void* d_out, int out_size)
{
    const float* x   = (const float*)d_in[0];
    const float* Wq  = (const float*)d_in[1];
    const float* bq  = (const float*)d_in[2];
    const float* Wk  = (const float*)d_in[3];
    const float* bk  = (const float*)d_in[4];
    const float* Wv  = (const float*)d_in[5];
    const float* bv  = (const float*)d_in[6];
    const float* Wp  = (const float*)d_in[7];
    const float* bp  = (const float*)d_in[8];
    const float* rph = (const float*)d_in[9];
    const float* rpw = (const float*)d_in[10];
    const float* Aq  = (const float*)d_in[11];
    const float* Bq  = (const float*)d_in[12];
    const float* Ak  = (const float*)d_in[13];
    const float* Bk  = (const float*)d_in[14];
    const float* Av  = (const float*)d_in[15];
    const float* Bv  = (const float*)d_in[16];
    float* out = (float*)d_out;

    const int gemm_smem  = 4 * GBUF * (int)sizeof(float);                     // 73728
    const int flash_smem = (2 * 64 * LKS + 64 * LVS + 64 * LPS) * (int)sizeof(float); // 70656
    cudaFuncSetAttribute(gemm_qkvf, cudaFuncAttributeMaxDynamicSharedMemorySize, gemm_smem);
    cudaFuncSetAttribute(gemm_projf, cudaFuncAttributeMaxDynamicSharedMemorySize, gemm_smem);
    cudaFuncSetAttribute(flash3, cudaFuncAttributeMaxDynamicSharedMemorySize, flash_smem);

    round_x<<<NTOK * DIM / 1024, 256>>>(x);
    fuse_wt<<<dim3(24, 24, 4), 256>>>(Wq, Aq, Bq, Wk, Ak, Bk, Wv, Av, Bv, Wp);
    gemm_qkvf<<<dim3(18, 18), 256, gemm_smem>>>(bq, bk, bv);
    rel2<<<dim3(HEADS, G, 2), 256>>>(rph, rpw);
    flash3<<<dim3(NTOK / 64, HEADS), 128, flash_smem>>>();
    gemm_projf<<<dim3(6, 18), 256, gemm_smem>>>(bp, out);
}

// round 4
// speedup vs baseline: 4.7272x; 1.0961x over previous
#include <cuda_runtime.h>
#include <cstdint>

#define DIM 768
#define HEADS 12
#define HD 64
#define G 48
#define NTOK 2304
#define RANK 8
#define NKT 36      // 2304/64 k-tiles

// ---------------- scratch --------------------------------------------------
__device__ __align__(16) float g_x[NTOK*DIM];          // tf32-rounded x
__device__ __align__(16) float g_Wqkv[3*DIM*DIM];      // fused+transposed+rounded [n][k]
__device__ __align__(16) float g_Wp[DIM*DIM];          // transposed+rounded [n][k]
__device__ __align__(16) float g_q[HEADS*NTOK*HD];     // tf32-rounded
__device__ __align__(16) float g_k[HEADS*NTOK*HD];
__device__ __align__(16) float g_v[HEADS*NTOK*HD];
__device__ __align__(16) float g_relh[HEADS*NTOK*G];
__device__ __align__(16) float g_relw[HEADS*NTOK*G];
__device__ __align__(16) float g_ao[NTOK*DIM];         // tf32-rounded

// ---------------- helpers ---------------------------------------------------
__device__ __forceinline__ float tf32r(float f) {
    unsigned u; asm("cvt.rna.tf32.f32 %0, %1;" : "=r"(u) : "f"(f));
    return __uint_as_float(u);
}
__device__ __forceinline__ void mma8(float* d,
                                     float a0, float a1, float a2, float a3,
                                     float b0, float b1) {
    unsigned ua0 = __float_as_uint(a0), ua1 = __float_as_uint(a1);
    unsigned ua2 = __float_as_uint(a2), ua3 = __float_as_uint(a3);
    unsigned ub0 = __float_as_uint(b0), ub1 = __float_as_uint(b1);
    asm volatile("mma.sync.aligned.m16n8k8.row.col.f32.tf32.tf32.f32 "
                 "{%0,%1,%2,%3},{%4,%5,%6,%7},{%8,%9},{%0,%1,%2,%3};"
                 : "+f"(d[0]), "+f"(d[1]), "+f"(d[2]), "+f"(d[3])
                 : "r"(ua0), "r"(ua1), "r"(ua2), "r"(ua3), "r"(ub0), "r"(ub1));
}
__device__ __forceinline__ void cpa16(uint32_t dst, const float* src) {
    asm volatile("cp.async.cg.shared.global [%0], [%1], 16;" :: "r"(dst), "l"(src));
}
#define CP_COMMIT() asm volatile("cp.async.commit_group;")
#define CP_WAIT(n)  asm volatile("cp.async.wait_group " #n ";")

// ---------------- kernel 0: round x to tf32 --------------------------------
__global__ __launch_bounds__(256) void round_x(const float* __restrict__ x) {
    int i = (blockIdx.x * 256 + threadIdx.x) * 4;
    float4 v = *(const float4*)(x + i);
    float4 o = make_float4(tf32r(v.x), tf32r(v.y), tf32r(v.z), tf32r(v.w));
    *(float4*)(g_x + i) = o;
}

// ---------------- kernel 1: fuse LoRA + transpose + round -------------------
__global__ __launch_bounds__(256) void fuse_wt(
    const float* __restrict__ Wq, const float* __restrict__ Aq, const float* __restrict__ Bq,
    const float* __restrict__ Wk, const float* __restrict__ Ak, const float* __restrict__ Bk,
    const float* __restrict__ Wv, const float* __restrict__ Av, const float* __restrict__ Bv,
    const float* __restrict__ Wp)
{
    __shared__ float tb[32][33];
    int z = blockIdx.z;
    const float *W, *A = nullptr, *B = nullptr;
    float* O;
    if (z == 0)      { W = Wq; A = Aq; B = Bq; O = g_Wqkv; }
    else if (z == 1) { W = Wk; A = Ak; B = Bk; O = g_Wqkv + DIM*DIM; }
    else if (z == 2) { W = Wv; A = Av; B = Bv; O = g_Wqkv + 2*DIM*DIM; }
    else             { W = Wp;                 O = g_Wp; }
    int kb = blockIdx.y * 32, nb = blockIdx.x * 32;
    int tx = threadIdx.x & 31, ty = threadIdx.x >> 5;
#pragma unroll
    for (int s = 0; s < 4; s++)
        tb[ty + 8 * s][tx] = W[(kb + ty + 8 * s) * DIM + nb + tx];
    __syncthreads();
#pragma unroll
    for (int s = 0; s < 4; s++) {
        int n = nb + ty + 8 * s;
        int k = kb + tx;
        float v = tb[tx][ty + 8 * s];
        if (z < 3) {
#pragma unroll
            for (int r = 0; r < RANK; r++)
                v += A[k * RANK + r] * B[r * DIM + n];
        }
        O[n * DIM + k] = tf32r(v);
    }
}

// ---------------- GEMM core (templated n-tile): 128m x (NJ*16)n, k=32 x2buf-
#define LDA 36
#define GBUFA (128*LDA)
template<int NJ>   // NJ*16 = n-tile width; NJ*8 = per-warp n-width
__device__ __forceinline__ void gemm_body_t(const float* __restrict__ Ain,
                                            const float* __restrict__ Btn,
                                            float acc[2][NJ][4], float* sm)
{
    const int NROWS = NJ * 16;           // B tile rows
    const int GBUFB = NROWS * LDA;
    int tid = threadIdx.x;
    int w = tid >> 5, l = tid & 31, g = l >> 2, t = l & 3;
    int wm = w >> 1, wn = w & 1;
    float* AS0 = sm;                 float* AS1 = AS0 + GBUFA;
    float* BS0 = AS1 + GBUFA;        float* BS1 = BS0 + GBUFB;
    uint32_t as0 = (uint32_t)__cvta_generic_to_shared(AS0);
    uint32_t as1 = (uint32_t)__cvta_generic_to_shared(AS1);
    uint32_t bs0 = (uint32_t)__cvta_generic_to_shared(BS0);
    uint32_t bs1 = (uint32_t)__cvta_generic_to_shared(BS1);

#pragma unroll
    for (int s = 0; s < 4; s++) {
        int id4 = tid + s * 256;
        int r = id4 >> 3, kc = (id4 & 7) * 4;
        cpa16(as0 + (r * LDA + kc) * 4, Ain + r * DIM + kc);
    }
#pragma unroll
    for (int s = 0; s < NJ / 2; s++) {
        int id4 = tid + s * 256;
        int r = id4 >> 3, kc = (id4 & 7) * 4;
        cpa16(bs0 + (r * LDA + kc) * 4, Btn + r * DIM + kc);
    }
    CP_COMMIT();

    for (int c = 0; c < 24; c++) {
        int buf = c & 1;
        if (c < 23) {
            uint32_t ad = buf ? as0 : as1;
            uint32_t bd = buf ? bs0 : bs1;
            int k0 = (c + 1) * 32;
#pragma unroll
            for (int s = 0; s < 4; s++) {
                int id4 = tid + s * 256;
                int r = id4 >> 3, kc = (id4 & 7) * 4;
                cpa16(ad + (r * LDA + kc) * 4, Ain + r * DIM + k0 + kc);
            }
#pragma unroll
            for (int s = 0; s < NJ / 2; s++) {
                int id4 = tid + s * 256;
                int r = id4 >> 3, kc = (id4 & 7) * 4;
                cpa16(bd + (r * LDA + kc) * 4, Btn + r * DIM + k0 + kc);
            }
            CP_COMMIT();
            CP_WAIT(1);
        } else {
            CP_WAIT(0);
        }
        __syncthreads();
        const float* As = buf ? AS1 : AS0;
        const float* Bs = buf ? BS1 : BS0;
#pragma unroll
        for (int ks = 0; ks < 4; ks++) {
            int kb = ks * 8;
            float a[2][4];
#pragma unroll
            for (int i = 0; i < 2; i++) {
                int r = wm * 32 + i * 16;
                a[i][0] = As[(r + g) * LDA + kb + t];
                a[i][1] = As[(r + g + 8) * LDA + kb + t];
                a[i][2] = As[(r + g) * LDA + kb + t + 4];
                a[i][3] = As[(r + g + 8) * LDA + kb + t + 4];
            }
#pragma unroll
            for (int j = 0; j < NJ; j++) {
                int n = wn * (NJ * 8) + j * 8;
                float b0 = Bs[(n + g) * LDA + kb + t];
                float b1 = Bs[(n + g) * LDA + kb + t + 4];
                mma8(acc[0][j], a[0][0], a[0][1], a[0][2], a[0][3], b0, b1);
                mma8(acc[1][j], a[1][0], a[1][1], a[1][2], a[1][3], b0, b1);
            }
        }
        __syncthreads();
    }
}

// ---------------- kernel 2: fused QKV GEMM (128m x 64n tiles) --------------
__global__ __launch_bounds__(256, 2) void gemm_qkvf(
    const float* __restrict__ bq, const float* __restrict__ bk, const float* __restrict__ bv)
{
    extern __shared__ float sm[];
    int m0 = blockIdx.y * 128, n0 = blockIdx.x * 64;
    float acc[2][4][4];
#pragma unroll
    for (int i = 0; i < 2; i++)
#pragma unroll
        for (int j = 0; j < 4; j++)
#pragma unroll
            for (int e = 0; e < 4; e++) acc[i][j][e] = 0.f;
    gemm_body_t<4>(g_x + m0 * DIM, g_Wqkv + n0 * DIM, acc, sm);

    int z = n0 / DIM;
    int nb = n0 - z * DIM;
    const float* bias = (z == 0) ? bq : (z == 1) ? bk : bv;
    float* outp       = (z == 0) ? g_q : (z == 1) ? g_k : g_v;
    int tid = threadIdx.x;
    int w = tid >> 5, l = tid & 31, g = l >> 2, t = l & 3;
    int wm = w >> 1, wn = w & 1;
#pragma unroll
    for (int i = 0; i < 2; i++) {
        int r0 = m0 + wm * 32 + i * 16 + g;
#pragma unroll
        for (int j = 0; j < 4; j++) {
            int c = nb + wn * 32 + j * 8 + t * 2;
            int h = c >> 6, cc = c & 63;
            float2 v0 = make_float2(tf32r(acc[i][j][0] + bias[c]),
                                    tf32r(acc[i][j][1] + bias[c + 1]));
            float2 v1 = make_float2(tf32r(acc[i][j][2] + bias[c]),
                                    tf32r(acc[i][j][3] + bias[c + 1]));
            *(float2*)&outp[h * (NTOK * HD) + r0 * HD + cc] = v0;
            *(float2*)&outp[h * (NTOK * HD) + (r0 + 8) * HD + cc] = v1;
        }
    }
}

// ---------------- kernel 5: output projection (128m x 64n tiles) ------------
__global__ __launch_bounds__(256, 2) void gemm_projf(
    const float* __restrict__ bp, float* __restrict__ out)
{
    extern __shared__ float sm[];
    int m0 = blockIdx.y * 128, n0 = blockIdx.x * 64;
    float acc[2][4][4];
#pragma unroll
    for (int i = 0; i < 2; i++)
#pragma unroll
        for (int j = 0; j < 4; j++)
#pragma unroll
            for (int e = 0; e < 4; e++) acc[i][j][e] = 0.f;
    gemm_body_t<4>(g_ao + m0 * DIM, g_Wp + n0 * DIM, acc, sm);

    int tid = threadIdx.x;
    int w = tid >> 5, l = tid & 31, g = l >> 2, t = l & 3;
    int wm = w >> 1, wn = w & 1;
#pragma unroll
    for (int i = 0; i < 2; i++) {
        int r0 = m0 + wm * 32 + i * 16 + g;
#pragma unroll
        for (int j = 0; j < 4; j++) {
            int c = n0 + wn * 32 + j * 8 + t * 2;
            float2 v0 = make_float2(acc[i][j][0] + bp[c], acc[i][j][1] + bp[c + 1]);
            float2 v1 = make_float2(acc[i][j][2] + bp[c], acc[i][j][3] + bp[c + 1]);
            *(float2*)&out[r0 * DIM + c] = v0;
            *(float2*)&out[(r0 + 8) * DIM + c] = v1;
        }
    }
}

// ---------------- kernel 3: rel-pos tables via tensor cores ----------------
// per block (head, p, z): C[48x48] = Q[48x64] * R^T, R[j][c] = rp[47-j][c]
#define RLD 68
__global__ __launch_bounds__(192) void rel_mma(
    const float* __restrict__ rph, const float* __restrict__ rpw)
{
    __shared__ float qs[48 * RLD];
    __shared__ float rp[48 * RLD];
    int head = blockIdx.x, p = blockIdx.y, z = blockIdx.z;
    int tid = threadIdx.x;
    const float* qhead = g_q + head * (NTOK * HD);
    const float* rpsrc = (z == 0) ? rph : rpw;

#pragma unroll
    for (int s = 0; s < 4; s++) {
        int id4 = tid + s * 192;              // 768 float4 = 48 x 64
        int r = id4 >> 4, c = (id4 & 15) * 4;
        int n = (z == 0) ? (p * G + r) : (r * G + p);
        *(float4*)&qs[r * RLD + c] = *(const float4*)(qhead + n * HD + c);  // already tf32
        float4 rv = *(const float4*)(rpsrc + (p + r) * HD + c);
        float4 ro = make_float4(tf32r(rv.x), tf32r(rv.y), tf32r(rv.z), tf32r(rv.w));
        *(float4*)&rp[r * RLD + c] = ro;
    }
    __syncthreads();

    int w = tid >> 5, l = tid & 31, g = l >> 2, t = l & 3;
    float acc[3][4];
#pragma unroll
    for (int i = 0; i < 3; i++)
#pragma unroll
        for (int e = 0; e < 4; e++) acc[i][e] = 0.f;

#pragma unroll
    for (int ks = 0; ks < 8; ks++) {
        int kb = ks * 8;
        int brow = 47 - (w * 8 + g);          // B[n][k] = rp[47-n][k]
        float b0 = rp[brow * RLD + kb + t];
        float b1 = rp[brow * RLD + kb + t + 4];
#pragma unroll
        for (int i = 0; i < 3; i++) {
            int r = i * 16;
            float a0 = qs[(r + g) * RLD + kb + t];
            float a1 = qs[(r + g + 8) * RLD + kb + t];
            float a2 = qs[(r + g) * RLD + kb + t + 4];
            float a3 = qs[(r + g + 8) * RLD + kb + t + 4];
            mma8(acc[i], a0, a1, a2, a3, b0, b1);
        }
    }

    float* dst = (z == 0) ? g_relh : g_relw;
    int j = w * 8 + t * 2;
#pragma unroll
    for (int i = 0; i < 3; i++) {
        int r0 = i * 16 + g;
        int n0 = (z == 0) ? (p * G + r0)     : (r0 * G + p);
        int n1 = (z == 0) ? (p * G + r0 + 8) : ((r0 + 8) * G + p);
        *(float2*)&dst[(head * NTOK + n0) * G + j] = make_float2(acc[i][0], acc[i][1]);
        *(float2*)&dst[(head * NTOK + n1) * G + j] = make_float2(acc[i][2], acc[i][3]);
    }
}

// ---------------- kernel 4: flash attention (cp.async pipelined) -----------
#define LKS 68
#define LVS 72
#define LPS 68
__global__ __launch_bounds__(128, 3) void flash3()
{
    extern __shared__ float sm[];
    float* Kb0 = sm;
    float* Kb1 = Kb0 + 64 * LKS;
    float* Vs  = Kb1 + 64 * LKS;
    float* Ps  = Vs + 64 * LVS;
    uint32_t kb0a = (uint32_t)__cvta_generic_to_shared(Kb0);
    uint32_t kb1a = (uint32_t)__cvta_generic_to_shared(Kb1);
    uint32_t vsa  = (uint32_t)__cvta_generic_to_shared(Vs);

    int tile = blockIdx.x, head = blockIdx.y;
    int tid = threadIdx.x, w = tid >> 5, l = tid & 31, g = l >> 2, t = l & 3;
    const float* qb    = g_q + head * (NTOK * HD) + tile * 64 * HD;
    const float* kbase = g_k + head * (NTOK * HD);
    const float* vbase = g_v + head * (NTOK * HD);

#pragma unroll
    for (int s = 0; s < 8; s++) {
        int id4 = tid + s * 128;
        int r = id4 >> 4, c = (id4 & 15) * 4;
        float4 v = *(const float4*)(qb + id4 * 4);
        float4 o = make_float4(v.x * 0.125f, v.y * 0.125f, v.z * 0.125f, v.w * 0.125f);
        *(float4*)&Ps[r * LPS + c] = o;
    }
#pragma unroll
    for (int s = 0; s < 8; s++) {
        int id4 = tid + s * 128;
        int r = id4 >> 4, c = (id4 & 15) * 4;
        cpa16(kb0a + (r * LKS + c) * 4, kbase + id4 * 4);
    }
    CP_COMMIT();
    __syncthreads();

    float qf[8][4];
    int pr = w * 16;
#pragma unroll
    for (int ks = 0; ks < 8; ks++) {
        qf[ks][0] = Ps[(pr + g) * LPS + ks * 8 + t];
        qf[ks][1] = Ps[(pr + g + 8) * LPS + ks * 8 + t];
        qf[ks][2] = Ps[(pr + g) * LPS + ks * 8 + t + 4];
        qf[ks][3] = Ps[(pr + g + 8) * LPS + ks * 8 + t + 4];
    }

    int rg0 = tile * 64 + w * 16 + g;
    const float* rhb = g_relh + head * NTOK * G;
    const float* rwb = g_relw + head * NTOK * G;

    float o[8][4];
#pragma unroll
    for (int j = 0; j < 8; j++)
#pragma unroll
        for (int e = 0; e < 4; e++) o[j][e] = 0.f;
    float m0v = -1e30f, m1v = -1e30f, l0 = 0.f, l1 = 0.f;

    for (int kt = 0; kt < NKT; kt++) {
        const float* Ks = (kt & 1) ? Kb1 : Kb0;
        if (kt + 1 < NKT) {
            uint32_t dst = (kt & 1) ? kb0a : kb1a;
            const float* src = kbase + (kt + 1) * 64 * HD;
#pragma unroll
            for (int s = 0; s < 8; s++) {
                int id4 = tid + s * 128;
                int r = id4 >> 4, c = (id4 & 15) * 4;
                cpa16(dst + (r * LKS + c) * 4, src + id4 * 4);
            }
            CP_COMMIT();
        }
        {
            const float* src = vbase + kt * 64 * HD;
#pragma unroll
            for (int s = 0; s < 8; s++) {
                int id4 = tid + s * 128;
                int r = id4 >> 4, c = (id4 & 15) * 4;
                cpa16(vsa + (r * LVS + c) * 4, src + id4 * 4);
            }
            CP_COMMIT();
        }
        if (kt + 1 < NKT) { CP_WAIT(2); } else { CP_WAIT(1); }
        __syncthreads();

        float s4[8][4];
#pragma unroll
        for (int j = 0; j < 8; j++)
#pragma unroll
            for (int e = 0; e < 4; e++) s4[j][e] = 0.f;
#pragma unroll
        for (int ks = 0; ks < 8; ks++) {
#pragma unroll
            for (int j = 0; j < 8; j++) {
                float b0 = Ks[(j * 8 + g) * LKS + ks * 8 + t];
                float b1 = Ks[(j * 8 + g) * LKS + ks * 8 + t + 4];
                mma8(s4[j], qf[ks][0], qf[ks][1], qf[ks][2], qf[ks][3], b0, b1);
            }
        }

        int colbase = kt * 64;
        int khA = colbase / G;
        int khB = (colbase + 63) / G;
        float rhA0 = rhb[rg0 * G + khA],       rhB0 = rhb[rg0 * G + khB];
        float rhA1 = rhb[(rg0 + 8) * G + khA], rhB1 = rhb[(rg0 + 8) * G + khB];
#pragma unroll
        for (int j = 0; j < 8; j++) {
            int c0 = colbase + j * 8 + t * 2;
            int c1 = c0 + 1;
            int kh0 = c0 / G, kw0 = c0 - kh0 * G;
            int kh1 = c1 / G, kw1 = c1 - kh1 * G;
            s4[j][0] += ((kh0 == khA) ? rhA0 : rhB0) + rwb[rg0 * G + kw0];
            s4[j][1] += ((kh1 == khA) ? rhA0 : rhB0) + rwb[rg0 * G + kw1];
            s4[j][2] += ((kh0 == khA) ? rhA1 : rhB1) + rwb[(rg0 + 8) * G + kw0];
            s4[j][3] += ((kh1 == khA) ? rhA1 : rhB1) + rwb[(rg0 + 8) * G + kw1];
        }

        float mx0 = -1e30f, mx1 = -1e30f;
#pragma unroll
        for (int j = 0; j < 8; j++) {
            mx0 = fmaxf(mx0, fmaxf(s4[j][0], s4[j][1]));
            mx1 = fmaxf(mx1, fmaxf(s4[j][2], s4[j][3]));
        }
        mx0 = fmaxf(mx0, __shfl_xor_sync(0xffffffffu, mx0, 1));
        mx0 = fmaxf(mx0, __shfl_xor_sync(0xffffffffu, mx0, 2));
        mx1 = fmaxf(mx1, __shfl_xor_sync(0xffffffffu, mx1, 1));
        mx1 = fmaxf(mx1, __shfl_xor_sync(0xffffffffu, mx1, 2));
        float mn0 = fmaxf(m0v, mx0), mn1 = fmaxf(m1v, mx1);
        float sum0 = 0.f, sum1 = 0.f;
#pragma unroll
        for (int j = 0; j < 8; j++) {
            s4[j][0] = __expf(s4[j][0] - mn0);
            s4[j][1] = __expf(s4[j][1] - mn0);
            s4[j][2] = __expf(s4[j][2] - mn1);
            s4[j][3] = __expf(s4[j][3] - mn1);
            sum0 += s4[j][0] + s4[j][1];
            sum1 += s4[j][2] + s4[j][3];
        }
        sum0 += __shfl_xor_sync(0xffffffffu, sum0, 1);
        sum0 += __shfl_xor_sync(0xffffffffu, sum0, 2);
        sum1 += __shfl_xor_sync(0xffffffffu, sum1, 1);
        sum1 += __shfl_xor_sync(0xffffffffu, sum1, 2);
        float al0 = __expf(m0v - mn0), al1 = __expf(m1v - mn1);
        l0 = l0 * al0 + sum0;  l1 = l1 * al1 + sum1;
        m0v = mn0;  m1v = mn1;
#pragma unroll
        for (int j = 0; j < 8; j++) {
            o[j][0] *= al0; o[j][1] *= al0;
            o[j][2] *= al1; o[j][3] *= al1;
        }

#pragma unroll
        for (int j = 0; j < 8; j++) {
            int mc = j * 8 + t * 2;
            Ps[(pr + g) * LPS + mc]         = tf32r(s4[j][0]);
            Ps[(pr + g) * LPS + mc + 1]     = tf32r(s4[j][1]);
            Ps[(pr + g + 8) * LPS + mc]     = tf32r(s4[j][2]);
            Ps[(pr + g + 8) * LPS + mc + 1] = tf32r(s4[j][3]);
        }
        if (kt + 1 < NKT) { CP_WAIT(1); } else { CP_WAIT(0); }
        __syncthreads();

#pragma unroll
        for (int ms = 0; ms < 8; ms++) {
            float a0 = Ps[(pr + g) * LPS + ms * 8 + t];
            float a1 = Ps[(pr + g + 8) * LPS + ms * 8 + t];
            float a2 = Ps[(pr + g) * LPS + ms * 8 + t + 4];
            float a3 = Ps[(pr + g + 8) * LPS + ms * 8 + t + 4];
#pragma unroll
            for (int j = 0; j < 8; j++) {
                float b0 = Vs[(ms * 8 + t) * LVS + j * 8 + g];
                float b1 = Vs[(ms * 8 + t + 4) * LVS + j * 8 + g];
                mma8(o[j], a0, a1, a2, a3, b0, b1);
            }
        }
        __syncthreads();
    }

    float inv0 = 1.f / l0, inv1 = 1.f / l1;
    int nq0 = tile * 64 + w * 16 + g;
#pragma unroll
    for (int j = 0; j < 8; j++) {
        int c = head * HD + j * 8 + t * 2;
        float2 v0 = make_float2(tf32r(o[j][0] * inv0), tf32r(o[j][1] * inv0));
        float2 v1 = make_float2(tf32r(o[j][2] * inv1), tf32r(o[j][3] * inv1));
        *(float2*)&g_ao[nq0 * DIM + c] = v0;
        *(float2*)&g_ao[(nq0 + 8) * DIM + c] = v1;
    }
}

// ---------------- launch ----------------------------------------------------
extern "C" void kernel_launch(void* const* d_in, const int* in_sizes, int n_in,
                              void* d_out, int out_size)
{
    const float* x   = (const float*)d_in[0];
    const float* Wq  = (const float*)d_in[1];
    const float* bq  = (const float*)d_in[2];
    const float* Wk  = (const float*)d_in[3];
    const float* bk  = (const float*)d_in[4];
    const float* Wv  = (const float*)d_in[5];
    const float* bv  = (const float*)d_in[6];
    const float* Wp  = (const float*)d_in[7];
    const float* bp  = (const float*)d_in[8];
    const float* rph = (const float*)d_in[9];
    const float* rpw = (const float*)d_in[10];
    const float* Aq  = (const float*)d_in[11];
    const float* Bq  = (const float*)d_in[12];
    const float* Ak  = (const float*)d_in[13];
    const float* Bk  = (const float*)d_in[14];
    const float* Av  = (const float*)d_in[15];
    const float* Bv  = (const float*)d_in[16];
    float* out = (float*)d_out;

    const int gemm_smem  = (2 * GBUFA + 2 * 64 * LDA) * (int)sizeof(float);   // 55296
    const int flash_smem = (2 * 64 * LKS + 64 * LVS + 64 * LPS) * (int)sizeof(float);
    cudaFuncSetAttribute(gemm_qkvf, cudaFuncAttributeMaxDynamicSharedMemorySize, gemm_smem);
    cudaFuncSetAttribute(gemm_projf, cudaFuncAttributeMaxDynamicSharedMemorySize, gemm_smem);
    cudaFuncSetAttribute(flash3, cudaFuncAttributeMaxDynamicSharedMemorySize, flash_smem);

    round_x<<<NTOK * DIM / 1024, 256>>>(x);
    fuse_wt<<<dim3(24, 24, 4), 256>>>(Wq, Aq, Bq, Wk, Ak, Bk, Wv, Av, Bv, Wp);
    gemm_qkvf<<<dim3(36, 18), 256, gemm_smem>>>(bq, bk, bv);
    rel_mma<<<dim3(HEADS, G, 2), 192>>>(rph, rpw);
    flash3<<<dim3(NTOK / 64, HEADS), 128, flash_smem>>>();
    gemm_projf<<<dim3(12, 18), 256, gemm_smem>>>(bp, out);
}

// round 6
// speedup vs baseline: 5.2147x; 1.1031x over previous
#include <cuda_runtime.h>
#include <cstdint>

#define DIM 768
#define HEADS 12
#define HD 64
#define G 48
#define NTOK 2304
#define RANK 8
#define NKT 36      // 2304/64 k-tiles

// ---------------- scratch --------------------------------------------------
__device__ __align__(16) float g_x[NTOK*DIM];          // tf32-rounded x
__device__ __align__(16) float g_Wqkv[3*DIM*DIM];      // fused+transposed+rounded [n][k]
__device__ __align__(16) float g_Wp[DIM*DIM];          // transposed+rounded [n][k]
__device__ __align__(16) float g_q[HEADS*NTOK*HD];     // [h][m][c] tf32
__device__ __align__(16) float g_k[HEADS*NTOK*HD];     // [h][m][c] tf32
__device__ __align__(16) float g_v[HEADS*NTOK*HD];     // [h][c][m] TRANSPOSED tf32
__device__ __align__(16) float g_relh[HEADS*NTOK*G];
__device__ __align__(16) float g_relw[HEADS*NTOK*G];
__device__ __align__(16) float g_ao[NTOK*DIM];         // tf32-rounded

// ---------------- helpers ---------------------------------------------------
__device__ __forceinline__ float tf32r(float f) {
    unsigned u; asm("cvt.rna.tf32.f32 %0, %1;" : "=r"(u) : "f"(f));
    return __uint_as_float(u);
}
__device__ __forceinline__ void mma8(float* d,
                                     float a0, float a1, float a2, float a3,
                                     float b0, float b1) {
    unsigned ua0 = __float_as_uint(a0), ua1 = __float_as_uint(a1);
    unsigned ua2 = __float_as_uint(a2), ua3 = __float_as_uint(a3);
    unsigned ub0 = __float_as_uint(b0), ub1 = __float_as_uint(b1);
    asm volatile("mma.sync.aligned.m16n8k8.row.col.f32.tf32.tf32.f32 "
                 "{%0,%1,%2,%3},{%4,%5,%6,%7},{%8,%9},{%0,%1,%2,%3};"
                 : "+f"(d[0]), "+f"(d[1]), "+f"(d[2]), "+f"(d[3])
                 : "r"(ua0), "r"(ua1), "r"(ua2), "r"(ua3), "r"(ub0), "r"(ub1));
}
__device__ __forceinline__ void cpa16(uint32_t dst, const float* src) {
    asm volatile("cp.async.cg.shared.global [%0], [%1], 16;" :: "r"(dst), "l"(src));
}
#define CP_COMMIT() asm volatile("cp.async.commit_group;")
#define CP_WAIT(n)  asm volatile("cp.async.wait_group " #n ";")

// ---------------- kernel 0: round x to tf32 --------------------------------
__global__ __launch_bounds__(256) void round_x(const float* __restrict__ x) {
    int i = (blockIdx.x * 256 + threadIdx.x) * 4;
    float4 v = *(const float4*)(x + i);
    float4 o = make_float4(tf32r(v.x), tf32r(v.y), tf32r(v.z), tf32r(v.w));
    *(float4*)(g_x + i) = o;
}

// ---------------- kernel 1: fuse LoRA + transpose + round -------------------
__global__ __launch_bounds__(256) void fuse_wt(
    const float* __restrict__ Wq, const float* __restrict__ Aq, const float* __restrict__ Bq,
    const float* __restrict__ Wk, const float* __restrict__ Ak, const float* __restrict__ Bk,
    const float* __restrict__ Wv, const float* __restrict__ Av, const float* __restrict__ Bv,
    const float* __restrict__ Wp)
{
    __shared__ float tb[32][33];
    int z = blockIdx.z;
    const float *W, *A = nullptr, *B = nullptr;
    float* O;
    if (z == 0)      { W = Wq; A = Aq; B = Bq; O = g_Wqkv; }
    else if (z == 1) { W = Wk; A = Ak; B = Bk; O = g_Wqkv + DIM*DIM; }
    else if (z == 2) { W = Wv; A = Av; B = Bv; O = g_Wqkv + 2*DIM*DIM; }
    else             { W = Wp;                 O = g_Wp; }
    int kb = blockIdx.y * 32, nb = blockIdx.x * 32;
    int tx = threadIdx.x & 31, ty = threadIdx.x >> 5;
#pragma unroll
    for (int s = 0; s < 4; s++)
        tb[ty + 8 * s][tx] = W[(kb + ty + 8 * s) * DIM + nb + tx];
    __syncthreads();
#pragma unroll
    for (int s = 0; s < 4; s++) {
        int n = nb + ty + 8 * s;
        int k = kb + tx;
        float v = tb[tx][ty + 8 * s];
        if (z < 3) {
#pragma unroll
            for (int r = 0; r < RANK; r++)
                v += A[k * RANK + r] * B[r * DIM + n];
        }
        O[n * DIM + k] = tf32r(v);
    }
}

// ---------------- GEMM core (templated n-tile): 128m x (NJ*16)n, k=32 x2buf-
#define LDA 40
#define GBUFA (128*LDA)
template<int NJ>
__device__ __forceinline__ void gemm_body_t(const float* __restrict__ Ain,
                                            const float* __restrict__ Btn,
                                            float acc[2][NJ][4], float* sm)
{
    const int NROWS = NJ * 16;
    const int GBUFB = NROWS * LDA;
    int tid = threadIdx.x;
    int w = tid >> 5, l = tid & 31, g = l >> 2, t = l & 3;
    int wm = w >> 1, wn = w & 1;
    float* AS0 = sm;                 float* AS1 = AS0 + GBUFA;
    float* BS0 = AS1 + GBUFA;        float* BS1 = BS0 + GBUFB;
    uint32_t as0 = (uint32_t)__cvta_generic_to_shared(AS0);
    uint32_t as1 = (uint32_t)__cvta_generic_to_shared(AS1);
    uint32_t bs0 = (uint32_t)__cvta_generic_to_shared(BS0);
    uint32_t bs1 = (uint32_t)__cvta_generic_to_shared(BS1);

#pragma unroll
    for (int s = 0; s < 4; s++) {
        int id4 = tid + s * 256;
        int r = id4 >> 3, kc = (id4 & 7) * 4;
        cpa16(as0 + (r * LDA + kc) * 4, Ain + r * DIM + kc);
    }
#pragma unroll
    for (int s = 0; s < NJ / 2; s++) {
        int id4 = tid + s * 256;
        int r = id4 >> 3, kc = (id4 & 7) * 4;
        cpa16(bs0 + (r * LDA + kc) * 4, Btn + r * DIM + kc);
    }
    CP_COMMIT();

    for (int c = 0; c < 24; c++) {
        int buf = c & 1;
        if (c < 23) {
            uint32_t ad = buf ? as0 : as1;
            uint32_t bd = buf ? bs0 : bs1;
            int k0 = (c + 1) * 32;
#pragma unroll
            for (int s = 0; s < 4; s++) {
                int id4 = tid + s * 256;
                int r = id4 >> 3, kc = (id4 & 7) * 4;
                cpa16(ad + (r * LDA + kc) * 4, Ain + r * DIM + k0 + kc);
            }
#pragma unroll
            for (int s = 0; s < NJ / 2; s++) {
                int id4 = tid + s * 256;
                int r = id4 >> 3, kc = (id4 & 7) * 4;
                cpa16(bd + (r * LDA + kc) * 4, Btn + r * DIM + k0 + kc);
            }
            CP_COMMIT();
            CP_WAIT(1);
        } else {
            CP_WAIT(0);
        }
        __syncthreads();
        const float* As = buf ? AS1 : AS0;
        const float* Bs = buf ? BS1 : BS0;
#pragma unroll
        for (int ks = 0; ks < 4; ks++) {
            int kb = ks * 8 + 2 * t;      // k=t -> phys 2t, k=t+4 -> phys 2t+1
            float2 alo[2], ahi[2];
#pragma unroll
            for (int i = 0; i < 2; i++) {
                int r = wm * 32 + i * 16;
                alo[i] = *(const float2*)&As[(r + g) * LDA + kb];
                ahi[i] = *(const float2*)&As[(r + g + 8) * LDA + kb];
            }
#pragma unroll
            for (int j = 0; j < NJ; j++) {
                int n = wn * (NJ * 8) + j * 8;
                float2 b = *(const float2*)&Bs[(n + g) * LDA + kb];
                mma8(acc[0][j], alo[0].x, ahi[0].x, alo[0].y, ahi[0].y, b.x, b.y);
                mma8(acc[1][j], alo[1].x, ahi[1].x, alo[1].y, ahi[1].y, b.x, b.y);
            }
        }
        __syncthreads();
    }
}

// ---------------- kernel 2: fused QKV GEMM (128m x 64n tiles) --------------
__global__ __launch_bounds__(256, 2) void gemm_qkvf(
    const float* __restrict__ bq, const float* __restrict__ bk, const float* __restrict__ bv)
{
    extern __shared__ float sm[];
    int m0 = blockIdx.y * 128, n0 = blockIdx.x * 64;
    float acc[2][4][4];
#pragma unroll
    for (int i = 0; i < 2; i++)
#pragma unroll
        for (int j = 0; j < 4; j++)
#pragma unroll
            for (int e = 0; e < 4; e++) acc[i][j][e] = 0.f;
    gemm_body_t<4>(g_x + m0 * DIM, g_Wqkv + n0 * DIM, acc, sm);

    int z = n0 / DIM;
    int nb = n0 - z * DIM;
    const float* bias = (z == 0) ? bq : (z == 1) ? bk : bv;
    float* outp       = (z == 0) ? g_q : (z == 1) ? g_k : g_v;
    int tid = threadIdx.x;
    int w = tid >> 5, l = tid & 31, g = l >> 2, t = l & 3;
    int wm = w >> 1, wn = w & 1;
#pragma unroll
    for (int i = 0; i < 2; i++) {
        int r0 = m0 + wm * 32 + i * 16 + g;
#pragma unroll
        for (int j = 0; j < 4; j++) {
            int c = nb + wn * 32 + j * 8 + t * 2;
            int h = c >> 6, cc = c & 63;
            float e0 = tf32r(acc[i][j][0] + bias[c]);
            float e1 = tf32r(acc[i][j][1] + bias[c + 1]);
            float e2 = tf32r(acc[i][j][2] + bias[c]);
            float e3 = tf32r(acc[i][j][3] + bias[c + 1]);
            if (z == 2) {   // V: transposed layout [h][c][m]
                float* vb = outp + h * (NTOK * HD);
                vb[cc * NTOK + r0]           = e0;
                vb[(cc + 1) * NTOK + r0]     = e1;
                vb[cc * NTOK + r0 + 8]       = e2;
                vb[(cc + 1) * NTOK + r0 + 8] = e3;
            } else {
                *(float2*)&outp[h * (NTOK * HD) + r0 * HD + cc] = make_float2(e0, e1);
                *(float2*)&outp[h * (NTOK * HD) + (r0 + 8) * HD + cc] = make_float2(e2, e3);
            }
        }
    }
}

// ---------------- kernel 5: output projection (128m x 64n tiles) ------------
__global__ __launch_bounds__(256, 2) void gemm_projf(
    const float* __restrict__ bp, float* __restrict__ out)
{
    extern __shared__ float sm[];
    int m0 = blockIdx.y * 128, n0 = blockIdx.x * 64;
    float acc[2][4][4];
#pragma unroll
    for (int i = 0; i < 2; i++)
#pragma unroll
        for (int j = 0; j < 4; j++)
#pragma unroll
            for (int e = 0; e < 4; e++) acc[i][j][e] = 0.f;
    gemm_body_t<4>(g_ao + m0 * DIM, g_Wp + n0 * DIM, acc, sm);

    int tid = threadIdx.x;
    int w = tid >> 5, l = tid & 31, g = l >> 2, t = l & 3;
    int wm = w >> 1, wn = w & 1;
#pragma unroll
    for (int i = 0; i < 2; i++) {
        int r0 = m0 + wm * 32 + i * 16 + g;
#pragma unroll
        for (int j = 0; j < 4; j++) {
            int c = n0 + wn * 32 + j * 8 + t * 2;
            float2 v0 = make_float2(acc[i][j][0] + bp[c], acc[i][j][1] + bp[c + 1]);
            float2 v1 = make_float2(acc[i][j][2] + bp[c], acc[i][j][3] + bp[c + 1]);
            *(float2*)&out[r0 * DIM + c] = v0;
            *(float2*)&out[(r0 + 8) * DIM + c] = v1;
        }
    }
}

// ---------------- kernel 3: rel-pos tables via tensor cores ----------------
#define RLD 68
__global__ __launch_bounds__(192) void rel_mma(
    const float* __restrict__ rph, const float* __restrict__ rpw)
{
    __shared__ float qs[48 * RLD];
    __shared__ float rp[48 * RLD];
    int head = blockIdx.x, p = blockIdx.y, z = blockIdx.z;
    int tid = threadIdx.x;
    const float* qhead = g_q + head * (NTOK * HD);
    const float* rpsrc = (z == 0) ? rph : rpw;

#pragma unroll
    for (int s = 0; s < 4; s++) {
        int id4 = tid + s * 192;
        int r = id4 >> 4, c = (id4 & 15) * 4;
        int n = (z == 0) ? (p * G + r) : (r * G + p);
        *(float4*)&qs[r * RLD + c] = *(const float4*)(qhead + n * HD + c);
        float4 rv = *(const float4*)(rpsrc + (p + r) * HD + c);
        float4 ro = make_float4(tf32r(rv.x), tf32r(rv.y), tf32r(rv.z), tf32r(rv.w));
        *(float4*)&rp[r * RLD + c] = ro;
    }
    __syncthreads();

    int w = tid >> 5, l = tid & 31, g = l >> 2, t = l & 3;
    float acc[3][4];
#pragma unroll
    for (int i = 0; i < 3; i++)
#pragma unroll
        for (int e = 0; e < 4; e++) acc[i][e] = 0.f;

#pragma unroll
    for (int ks = 0; ks < 8; ks++) {
        int kb = ks * 8;
        int brow = 47 - (w * 8 + g);
        float b0 = rp[brow * RLD + kb + t];
        float b1 = rp[brow * RLD + kb + t + 4];
#pragma unroll
        for (int i = 0; i < 3; i++) {
            int r = i * 16;
            float a0 = qs[(r + g) * RLD + kb + t];
            float a1 = qs[(r + g + 8) * RLD + kb + t];
            float a2 = qs[(r + g) * RLD + kb + t + 4];
            float a3 = qs[(r + g + 8) * RLD + kb + t + 4];
            mma8(acc[i], a0, a1, a2, a3, b0, b1);
        }
    }

    float* dst = (z == 0) ? g_relh : g_relw;
    int j = w * 8 + t * 2;
#pragma unroll
    for (int i = 0; i < 3; i++) {
        int r0 = i * 16 + g;
        int n0 = (z == 0) ? (p * G + r0)     : (r0 * G + p);
        int n1 = (z == 0) ? (p * G + r0 + 8) : ((r0 + 8) * G + p);
        *(float2*)&dst[(head * NTOK + n0) * G + j] = make_float2(acc[i][0], acc[i][1]);
        *(float2*)&dst[(head * NTOK + n1) * G + j] = make_float2(acc[i][2], acc[i][3]);
    }
}

// ---------------- kernel 4: flash attention (float2 frags, VT) -------------
#define LKS 72
#define LVT 72
#define LPS 72
__global__ __launch_bounds__(128, 3) void flash3()
{
    extern __shared__ float sm[];
    float* Kb0 = sm;
    float* Kb1 = Kb0 + 64 * LKS;
    float* Vt  = Kb1 + 64 * LKS;        // [c][m] 64x64
    float* Ps  = Vt + 64 * LVT;         // Q staging, then P
    uint32_t kb0a = (uint32_t)__cvta_generic_to_shared(Kb0);
    uint32_t kb1a = (uint32_t)__cvta_generic_to_shared(Kb1);
    uint32_t vta  = (uint32_t)__cvta_generic_to_shared(Vt);

    int tile = blockIdx.x, head = blockIdx.y;
    int tid = threadIdx.x, w = tid >> 5, l = tid & 31, g = l >> 2, t = l & 3;
    const float* qb    = g_q + head * (NTOK * HD) + tile * 64 * HD;
    const float* kbase = g_k + head * (NTOK * HD);
    const float* vtb   = g_v + head * (NTOK * HD);   // [c][m]

    // stage Q (x 0.125)
#pragma unroll
    for (int s = 0; s < 8; s++) {
        int id4 = tid + s * 128;
        int r = id4 >> 4, c = (id4 & 15) * 4;
        float4 v = *(const float4*)(qb + id4 * 4);
        float4 o = make_float4(v.x * 0.125f, v.y * 0.125f, v.z * 0.125f, v.w * 0.125f);
        *(float4*)&Ps[r * LPS + c] = o;
    }
    // issue K(0)
#pragma unroll
    for (int s = 0; s < 8; s++) {
        int id4 = tid + s * 128;
        int r = id4 >> 4, c = (id4 & 15) * 4;
        cpa16(kb0a + (r * LKS + c) * 4, kbase + id4 * 4);
    }
    CP_COMMIT();
    __syncthreads();

    // Q fragments: float2 pairs (k=t -> phys 2t, k=t+4 -> phys 2t+1)
    float qf[8][4];
    int pr = w * 16;
#pragma unroll
    for (int ks = 0; ks < 8; ks++) {
        float2 lo = *(const float2*)&Ps[(pr + g) * LPS + ks * 8 + 2 * t];
        float2 hi = *(const float2*)&Ps[(pr + g + 8) * LPS + ks * 8 + 2 * t];
        qf[ks][0] = lo.x; qf[ks][1] = hi.x; qf[ks][2] = lo.y; qf[ks][3] = hi.y;
    }

    int rg0 = tile * 64 + w * 16 + g;
    const float* rhb = g_relh + head * NTOK * G;
    const float* rwb = g_relw + head * NTOK * G;

    float o[8][4];
#pragma unroll
    for (int j = 0; j < 8; j++)
#pragma unroll
        for (int e = 0; e < 4; e++) o[j][e] = 0.f;
    float m0v = -1e30f, m1v = -1e30f, l0 = 0.f, l1 = 0.f;

    for (int kt = 0; kt < NKT; kt++) {
        const float* Ks = (kt & 1) ? Kb1 : Kb0;
        if (kt + 1 < NKT) {
            uint32_t dst = (kt & 1) ? kb0a : kb1a;
            const float* src = kbase + (kt + 1) * 64 * HD;
#pragma unroll
            for (int s = 0; s < 8; s++) {
                int id4 = tid + s * 128;
                int r = id4 >> 4, c = (id4 & 15) * 4;
                cpa16(dst + (r * LKS + c) * 4, src + id4 * 4);
            }
            CP_COMMIT();
        }
        {   // V^T tile: 64 rows (c) x 64 cols (m) = 1024 float4
            const float* src = vtb + kt * 64;
#pragma unroll
            for (int s = 0; s < 8; s++) {
                int id4 = tid + s * 128;
                int r = id4 >> 4, seg = (id4 & 15) * 4;
                cpa16(vta + (r * LVT + seg) * 4, src + r * NTOK + seg);
            }
            CP_COMMIT();
        }
        if (kt + 1 < NKT) { CP_WAIT(2); } else { CP_WAIT(1); }
        __syncthreads();

        // S = Q K^T (float2 B frags)
        float s4[8][4];
#pragma unroll
        for (int j = 0; j < 8; j++)
#pragma unroll
            for (int e = 0; e < 4; e++) s4[j][e] = 0.f;
#pragma unroll
        for (int ks = 0; ks < 8; ks++) {
            int kb = ks * 8 + 2 * t;
#pragma unroll
            for (int j = 0; j < 8; j++) {
                float2 b = *(const float2*)&Ks[(j * 8 + g) * LKS + kb];
                mma8(s4[j], qf[ks][0], qf[ks][1], qf[ks][2], qf[ks][3], b.x, b.y);
            }
        }

        // decomposed rel-pos bias
        int colbase = kt * 64;
        int khA = colbase / G;
        int khB = (colbase + 63) / G;
        float rhA0 = rhb[rg0 * G + khA],       rhB0 = rhb[rg0 * G + khB];
        float rhA1 = rhb[(rg0 + 8) * G + khA], rhB1 = rhb[(rg0 + 8) * G + khB];
#pragma unroll
        for (int j = 0; j < 8; j++) {
            int c0 = colbase + j * 8 + t * 2;
            int c1 = c0 + 1;
            int kh0 = c0 / G, kw0 = c0 - kh0 * G;
            int kh1 = c1 / G, kw1 = c1 - kh1 * G;
            s4[j][0] += ((kh0 == khA) ? rhA0 : rhB0) + rwb[rg0 * G + kw0];
            s4[j][1] += ((kh1 == khA) ? rhA0 : rhB0) + rwb[rg0 * G + kw1];
            s4[j][2] += ((kh0 == khA) ? rhA1 : rhB1) + rwb[(rg0 + 8) * G + kw0];
            s4[j][3] += ((kh1 == khA) ? rhA1 : rhB1) + rwb[(rg0 + 8) * G + kw1];
        }

        // online softmax
        float mx0 = -1e30f, mx1 = -1e30f;
#pragma unroll
        for (int j = 0; j < 8; j++) {
            mx0 = fmaxf(mx0, fmaxf(s4[j][0], s4[j][1]));
            mx1 = fmaxf(mx1, fmaxf(s4[j][2], s4[j][3]));
        }
        mx0 = fmaxf(mx0, __shfl_xor_sync(0xffffffffu, mx0, 1));
        mx0 = fmaxf(mx0, __shfl_xor_sync(0xffffffffu, mx0, 2));
        mx1 = fmaxf(mx1, __shfl_xor_sync(0xffffffffu, mx1, 1));
        mx1 = fmaxf(mx1, __shfl_xor_sync(0xffffffffu, mx1, 2));
        float mn0 = fmaxf(m0v, mx0), mn1 = fmaxf(m1v, mx1);
        float sum0 = 0.f, sum1 = 0.f;
#pragma unroll
        for (int j = 0; j < 8; j++) {
            s4[j][0] = __expf(s4[j][0] - mn0);
            s4[j][1] = __expf(s4[j][1] - mn0);
            s4[j][2] = __expf(s4[j][2] - mn1);
            s4[j][3] = __expf(s4[j][3] - mn1);
            sum0 += s4[j][0] + s4[j][1];
            sum1 += s4[j][2] + s4[j][3];
        }
        sum0 += __shfl_xor_sync(0xffffffffu, sum0, 1);
        sum0 += __shfl_xor_sync(0xffffffffu, sum0, 2);
        sum1 += __shfl_xor_sync(0xffffffffu, sum1, 1);
        sum1 += __shfl_xor_sync(0xffffffffu, sum1, 2);
        float al0 = __expf(m0v - mn0), al1 = __expf(m1v - mn1);
        l0 = l0 * al0 + sum0;  l1 = l1 * al1 + sum1;
        m0v = mn0;  m1v = mn1;
#pragma unroll
        for (int j = 0; j < 8; j++) {
            o[j][0] *= al0; o[j][1] *= al0;
            o[j][2] *= al1; o[j][3] *= al1;
        }

        // write P (tf32) as float2 pairs — natural column order
#pragma unroll
        for (int j = 0; j < 8; j++) {
            int mc = j * 8 + t * 2;
            *(float2*)&Ps[(pr + g) * LPS + mc]     = make_float2(tf32r(s4[j][0]), tf32r(s4[j][1]));
            *(float2*)&Ps[(pr + g + 8) * LPS + mc] = make_float2(tf32r(s4[j][2]), tf32r(s4[j][3]));
        }
        if (kt + 1 < NKT) { CP_WAIT(1); } else { CP_WAIT(0); }
        __syncthreads();

        // O += P V : A frags (P) and B frags (V^T) both as float2 pairs
#pragma unroll
        for (int ms = 0; ms < 8; ms++) {
            int mb = ms * 8 + 2 * t;    // logical k=t -> phys m 2t, k=t+4 -> 2t+1
            float2 alo = *(const float2*)&Ps[(pr + g) * LPS + mb];
            float2 ahi = *(const float2*)&Ps[(pr + g + 8) * LPS + mb];
#pragma unroll
            for (int j = 0; j < 8; j++) {
                float2 b = *(const float2*)&Vt[(j * 8 + g) * LVT + mb];
                mma8(o[j], alo.x, ahi.x, alo.y, ahi.y, b.x, b.y);
            }
        }
        __syncthreads();
    }

    // epilogue (tf32-rounded for the projection GEMM)
    float inv0 = 1.f / l0, inv1 = 1.f / l1;
    int nq0 = tile * 64 + w * 16 + g;
#pragma unroll
    for (int j = 0; j < 8; j++) {
        int c = head * HD + j * 8 + t * 2;
        float2 v0 = make_float2(tf32r(o[j][0] * inv0), tf32r(o[j][1] * inv0));
        float2 v1 = make_float2(tf32r(o[j][2] * inv1), tf32r(o[j][3] * inv1));
        *(float2*)&g_ao[nq0 * DIM + c] = v0;
        *(float2*)&g_ao[(nq0 + 8) * DIM + c] = v1;
    }
}

// ---------------- launch ----------------------------------------------------
extern "C" void kernel_launch(void* const* d_in, const int* in_sizes, int n_in,
                              void* d_out, int out_size)
{
    const float* x   = (const float*)d_in[0];
    const float* Wq  = (const float*)d_in[1];
    const float* bq  = (const float*)d_in[2];
    const float* Wk  = (const float*)d_in[3];
    const float* bk  = (const float*)d_in[4];
    const float* Wv  = (const float*)d_in[5];
    const float* bv  = (const float*)d_in[6];
    const float* Wp  = (const float*)d_in[7];
    const float* bp  = (const float*)d_in[8];
    const float* rph = (const float*)d_in[9];
    const float* rpw = (const float*)d_in[10];
    const float* Aq  = (const float*)d_in[11];
    const float* Bq  = (const float*)d_in[12];
    const float* Ak  = (const float*)d_in[13];
    const float* Bk  = (const float*)d_in[14];
    const float* Av  = (const float*)d_in[15];
    const float* Bv  = (const float*)d_in[16];
    float* out = (float*)d_out;

    const int gemm_smem  = (2 * GBUFA + 2 * 64 * LDA) * (int)sizeof(float);
    const int flash_smem = (2 * 64 * LKS + 64 * LVT + 64 * LPS) * (int)sizeof(float);
    cudaFuncSetAttribute(gemm_qkvf, cudaFuncAttributeMaxDynamicSharedMemorySize, gemm_smem);
    cudaFuncSetAttribute(gemm_projf, cudaFuncAttributeMaxDynamicSharedMemorySize, gemm_smem);
    cudaFuncSetAttribute(flash3, cudaFuncAttributeMaxDynamicSharedMemorySize, flash_smem);

    round_x<<<NTOK * DIM / 1024, 256>>>(x);
    fuse_wt<<<dim3(24, 24, 4), 256>>>(Wq, Aq, Bq, Wk, Ak, Bk, Wv, Av, Bv, Wp);
    gemm_qkvf<<<dim3(36, 18), 256, gemm_smem>>>(bq, bk, bv);
    rel_mma<<<dim3(HEADS, G, 2), 192>>>(rph, rpw);
    flash3<<<dim3(NTOK / 64, HEADS), 128, flash_smem>>>();
    gemm_projf<<<dim3(12, 18), 256, gemm_smem>>>(bp, out);
}